// round 1
// baseline (speedup 1.0000x reference)
#include <cuda_runtime.h>
#include <math.h>

#define L_   4096
#define DM_  1024
#define H_   16
#define DH_  64
#define BS_  64
#define W_   16
#define NB_  64
#define DFF_ 4096

// ---------------- scratch (static __device__ arrays; no allocations) ----------------
__device__ float g_H [L_ * DM_];   // LN1 output, reused for LN2 output
__device__ float g_Q [L_ * DM_];
__device__ float g_K [L_ * DM_];
__device__ float g_V [L_ * DM_];
__device__ float g_O [L_ * DM_];   // attention output (pre-Wo)
__device__ float g_X1[L_ * DM_];   // x + attn@Wo
__device__ float g_G [L_ * DFF_];  // gelu(h2@W1+b1)

// ---------------- helpers ----------------
__device__ __forceinline__ float block_sum(float val, float* red) {
    int t = threadIdx.x;
    #pragma unroll
    for (int o = 16; o > 0; o >>= 1) val += __shfl_xor_sync(0xffffffffu, val, o);
    __syncthreads();               // protect red from previous round
    if ((t & 31) == 0) red[t >> 5] = val;
    __syncthreads();
    if (t == 0) {
        float z = 0.f;
        #pragma unroll
        for (int i = 0; i < 8; i++) z += red[i];
        red[0] = z;
    }
    __syncthreads();
    return red[0];
}

__device__ __forceinline__ float gelu_f(float x) {
    // jax.nn.gelu approximate=True (tanh form)
    float x3 = x * x * x;
    return 0.5f * x * (1.f + tanhf(0.7978845608028654f * (x + 0.044715f * x3)));
}

// ---------------- LayerNorm: one block per row (DM=1024, 256 threads) ----------------
__global__ __launch_bounds__(256) void ln_kernel(const float* __restrict__ x,
                                                 const float* __restrict__ g,
                                                 const float* __restrict__ b,
                                                 float* __restrict__ out) {
    __shared__ float red[8];
    int row = blockIdx.x;
    const float* xr = x + (size_t)row * DM_;
    int t = threadIdx.x;
    float v[4];
    float s = 0.f;
    #pragma unroll
    for (int i = 0; i < 4; i++) { v[i] = xr[t + i * 256]; s += v[i]; }
    float mean = block_sum(s, red) * (1.f / DM_);
    float s2 = 0.f;
    #pragma unroll
    for (int i = 0; i < 4; i++) { float d = v[i] - mean; s2 += d * d; }
    float var = block_sum(s2, red) * (1.f / DM_);
    float inv = rsqrtf(var + 1e-5f);
    float* orow = out + (size_t)row * DM_;
    #pragma unroll
    for (int i = 0; i < 4; i++) {
        int c = t + i * 256;
        orow[c] = (v[i] - mean) * inv * g[c] + b[c];
    }
}

// ---------------- tiled fp32 GEMM: C = act(A@B + bias) + res ----------------
// 64x64 tile, BK=16, 256 threads, 4x4 per thread.
template<bool BIAS, bool RES, bool GELU_>
__global__ __launch_bounds__(256) void sgemm_kernel(const float* __restrict__ A,
                                                    const float* __restrict__ B,
                                                    const float* __restrict__ bias,
                                                    const float* __restrict__ res,
                                                    float* __restrict__ C,
                                                    int M, int N, int K) {
    __shared__ float As[16][68];
    __shared__ float Bs[16][68];
    int tid = threadIdx.x;
    int bm = blockIdx.y * 64, bn = blockIdx.x * 64;
    int ty = tid >> 4, tx = tid & 15;

    int arow = tid >> 2, ac4 = (tid & 3) * 4;
    int brow = tid >> 4, bc4 = (tid & 15) * 4;

    float acc[4][4];
    #pragma unroll
    for (int i = 0; i < 4; i++)
        #pragma unroll
        for (int j = 0; j < 4; j++) acc[i][j] = 0.f;

    for (int k0 = 0; k0 < K; k0 += 16) {
        float4 a = *(const float4*)(A + (size_t)(bm + arow) * K + k0 + ac4);
        As[ac4 + 0][arow] = a.x;
        As[ac4 + 1][arow] = a.y;
        As[ac4 + 2][arow] = a.z;
        As[ac4 + 3][arow] = a.w;
        *(float4*)(&Bs[brow][bc4]) = *(const float4*)(B + (size_t)(k0 + brow) * N + bn + bc4);
        __syncthreads();
        #pragma unroll
        for (int k = 0; k < 16; k++) {
            float4 av = *(float4*)(&As[k][ty * 4]);
            float4 bv = *(float4*)(&Bs[k][tx * 4]);
            acc[0][0] += av.x * bv.x; acc[0][1] += av.x * bv.y; acc[0][2] += av.x * bv.z; acc[0][3] += av.x * bv.w;
            acc[1][0] += av.y * bv.x; acc[1][1] += av.y * bv.y; acc[1][2] += av.y * bv.z; acc[1][3] += av.y * bv.w;
            acc[2][0] += av.z * bv.x; acc[2][1] += av.z * bv.y; acc[2][2] += av.z * bv.z; acc[2][3] += av.z * bv.w;
            acc[3][0] += av.w * bv.x; acc[3][1] += av.w * bv.y; acc[3][2] += av.w * bv.z; acc[3][3] += av.w * bv.w;
        }
        __syncthreads();
    }

    #pragma unroll
    for (int ii = 0; ii < 4; ii++) {
        int row = bm + ty * 4 + ii;
        int col = bn + tx * 4;
        float4 o;
        float vv[4];
        #pragma unroll
        for (int jj = 0; jj < 4; jj++) {
            float v = acc[ii][jj];
            if (BIAS) v += bias[col + jj];
            if (GELU_) v = gelu_f(v);
            vv[jj] = v;
        }
        if (RES) {
            float4 r = *(const float4*)(res + (size_t)row * N + col);
            vv[0] += r.x; vv[1] += r.y; vv[2] += r.z; vv[3] += r.w;
        }
        o.x = vv[0]; o.y = vv[1]; o.z = vv[2]; o.w = vv[3];
        *(float4*)(C + (size_t)row * N + col) = o;
    }
}

// ---------------- banded attention (flash-style online softmax) ----------------
// grid (NB, H), 256 threads. Thread t: query si = t&63, j-chunk jc = t>>6 (16 j's),
// holds partial acc[64] over its j-subset; combined at the end through smem.
__global__ __launch_bounds__(256) void attn_kernel(const float* __restrict__ Q,
                                                   const float* __restrict__ Kb,
                                                   const float* __restrict__ Vb,
                                                   const float* __restrict__ rel_emb,
                                                   float* __restrict__ O) {
    __shared__ float qs[BS_ * 65];
    __shared__ float kv[BS_ * 65];
    __shared__ float red1[4 * 64];
    __shared__ float red2[4 * 64];
    __shared__ float bias_s[258];
    __shared__ float invl_s[64];

    int n = blockIdx.x, h = blockIdx.y;
    int tid = threadIdx.x;
    int si = tid & 63, jc = tid >> 6;

    // load q (pre-scaled by 1/sqrt(DH)) and the per-head bias column
    for (int t = tid; t < BS_ * DH_; t += 256) {
        int i = t >> 6, d = t & 63;
        qs[i * 65 + d] = Q[(size_t)(n * BS_ + i) * DM_ + h * DH_ + d] * 0.125f;
    }
    for (int t = tid; t < 258; t += 256) bias_s[t] = rel_emb[t * H_ + h];

    float acc[64];
    #pragma unroll
    for (int d = 0; d < 64; d++) acc[d] = 0.f;
    float m_run = -1e30f, l_run = 0.f;

    int w0 = (n >= W_ - 1) ? 0 : (W_ - 1 - n);
    for (int w = w0; w < W_; w++) {
        int sb = n - (W_ - 1) + w;
        __syncthreads();  // kv free (prev iter done); also covers qs/bias on first iter
        for (int t = tid; t < BS_ * DH_; t += 256) {
            int j = t >> 6, d = t & 63;
            kv[j * 65 + d] = Kb[(size_t)(sb * BS_ + j) * DM_ + h * DH_ + d];
        }
        __syncthreads();

        // scores for (si, jc*16 .. jc*16+15)
        float s[16];
        #pragma unroll
        for (int jj = 0; jj < 16; jj++) s[jj] = 0.f;
        #pragma unroll 8
        for (int d = 0; d < 64; d++) {
            float qv = qs[si * 65 + d];
            #pragma unroll
            for (int jj = 0; jj < 16; jj++)
                s[jj] += qv * kv[(jc * 16 + jj) * 65 + d];
        }

        // bias + causal mask, local max
        float mx = -1e30f;
        #pragma unroll
        for (int jj = 0; jj < 16; jj++) {
            int j = jc * 16 + jj;
            int delta = (W_ - 1 - w) * 64 + si - j;
            int idx = min(delta, 256) + 1;
            idx = max(idx, 0);
            float val = s[jj] + bias_s[idx];
            if (w == W_ - 1 && j > si) val = -1e30f;
            s[jj] = val;
            mx = fmaxf(mx, val);
        }
        red1[jc * 64 + si] = mx;
        __syncthreads();   // all K reads done; red1 visible

        float m_new = m_run;
        #pragma unroll
        for (int c = 0; c < 4; c++) m_new = fmaxf(m_new, red1[c * 64 + si]);
        float lsum = 0.f;
        #pragma unroll
        for (int jj = 0; jj < 16; jj++) { s[jj] = __expf(s[jj] - m_new); lsum += s[jj]; }
        red2[jc * 64 + si] = lsum;

        // overwrite kv with V (safe: post-sync, no one reads K anymore)
        for (int t = tid; t < BS_ * DH_; t += 256) {
            int j = t >> 6, d = t & 63;
            kv[j * 65 + d] = Vb[(size_t)(sb * BS_ + j) * DM_ + h * DH_ + d];
        }
        __syncthreads();

        float rs = 0.f;
        #pragma unroll
        for (int c = 0; c < 4; c++) rs += red2[c * 64 + si];
        float scale = __expf(m_run - m_new);
        l_run = l_run * scale + rs;
        m_run = m_new;
        #pragma unroll
        for (int d = 0; d < 64; d++) acc[d] *= scale;
        #pragma unroll
        for (int jj = 0; jj < 16; jj++) {
            float p = s[jj];
            int j = jc * 16 + jj;
            #pragma unroll
            for (int d = 0; d < 64; d++)
                acc[d] += p * kv[j * 65 + d];
        }
    }

    // combine the 4 partial accumulators per query through smem (reuse kv)
    if (jc == 0) invl_s[si] = 1.f / l_run;
    __syncthreads();  // last PV reads of kv done
    #pragma unroll
    for (int c = 0; c < 4; c++) {
        if (jc == c) {
            if (c == 0) {
                #pragma unroll
                for (int d = 0; d < 64; d++) kv[si * 65 + d] = acc[d];
            } else {
                #pragma unroll
                for (int d = 0; d < 64; d++) kv[si * 65 + d] += acc[d];
            }
        }
        __syncthreads();
    }
    for (int t = tid; t < BS_ * DH_; t += 256) {
        int i = t >> 6, d = t & 63;
        O[(size_t)(n * BS_ + i) * DM_ + h * DH_ + d] = kv[i * 65 + d] * invl_s[i];
    }
}

// ---------------- launch ----------------
extern "C" void kernel_launch(void* const* d_in, const int* in_sizes, int n_in,
                              void* d_out, int out_size) {
    (void)in_sizes; (void)n_in; (void)out_size;
    const float* x      = (const float*)d_in[0];
    const float* Wq     = (const float*)d_in[1];
    const float* Wk     = (const float*)d_in[2];
    const float* Wv     = (const float*)d_in[3];
    const float* Wo     = (const float*)d_in[4];
    const float* rel    = (const float*)d_in[5];
    const float* ln1g   = (const float*)d_in[6];
    const float* ln1b   = (const float*)d_in[7];
    const float* ln2g   = (const float*)d_in[8];
    const float* ln2b   = (const float*)d_in[9];
    const float* W1     = (const float*)d_in[10];
    const float* b1     = (const float*)d_in[11];
    const float* W2     = (const float*)d_in[12];
    const float* b2     = (const float*)d_in[13];
    float* out = (float*)d_out;

    float *Hb, *Qb, *Kb, *Vb, *Ob, *X1, *Gb;
    cudaGetSymbolAddress((void**)&Hb, g_H);
    cudaGetSymbolAddress((void**)&Qb, g_Q);
    cudaGetSymbolAddress((void**)&Kb, g_K);
    cudaGetSymbolAddress((void**)&Vb, g_V);
    cudaGetSymbolAddress((void**)&Ob, g_O);
    cudaGetSymbolAddress((void**)&X1, g_X1);
    cudaGetSymbolAddress((void**)&Gb, g_G);

    // 1. h = LN1(x)
    ln_kernel<<<L_, 256>>>(x, ln1g, ln1b, Hb);

    // 2. Q, K, V
    dim3 g1(DM_ / 64, L_ / 64);
    sgemm_kernel<false, false, false><<<g1, 256>>>(Hb, Wq, nullptr, nullptr, Qb, L_, DM_, DM_);
    sgemm_kernel<false, false, false><<<g1, 256>>>(Hb, Wk, nullptr, nullptr, Kb, L_, DM_, DM_);
    sgemm_kernel<false, false, false><<<g1, 256>>>(Hb, Wv, nullptr, nullptr, Vb, L_, DM_, DM_);

    // 3. banded attention
    attn_kernel<<<dim3(NB_, H_), 256>>>(Qb, Kb, Vb, rel, Ob);

    // 4. x1 = x + O @ Wo
    sgemm_kernel<false, true, false><<<g1, 256>>>(Ob, Wo, nullptr, x, X1, L_, DM_, DM_);

    // 5. h2 = LN2(x1)  (reuse g_H)
    ln_kernel<<<L_, 256>>>(X1, ln2g, ln2b, Hb);

    // 6. G = gelu(h2 @ W1 + b1)
    sgemm_kernel<true, false, true><<<dim3(DFF_ / 64, L_ / 64), 256>>>(Hb, W1, b1, nullptr, Gb, L_, DFF_, DM_);

    // 7. out = x1 + G @ W2 + b2
    sgemm_kernel<true, true, false><<<g1, 256>>>(Gb, W2, b2, X1, out, L_, DM_, DFF_);
}

// round 2
// speedup vs baseline: 1.9833x; 1.9833x over previous
#include <cuda_runtime.h>
#include <math.h>

#define L_   4096
#define DM_  1024
#define H_   16
#define DH_  64
#define BS_  64
#define W_   16
#define NB_  64
#define DFF_ 4096

// ---------------- scratch (static __device__ arrays; no allocations) ----------------
__device__ float g_H [L_ * DM_];   // LN1 output, reused for LN2 output
__device__ float g_Q [L_ * DM_];
__device__ float g_K [L_ * DM_];
__device__ float g_V [L_ * DM_];
__device__ float g_O [L_ * DM_];   // attention output (pre-Wo)
__device__ float g_X1[L_ * DM_];   // x + attn@Wo
__device__ float g_G [L_ * DFF_];  // gelu(h2@W1+b1)

// ---------------- helpers ----------------
__device__ __forceinline__ float block_sum(float val, float* red) {
    int t = threadIdx.x;
    #pragma unroll
    for (int o = 16; o > 0; o >>= 1) val += __shfl_xor_sync(0xffffffffu, val, o);
    __syncthreads();
    if ((t & 31) == 0) red[t >> 5] = val;
    __syncthreads();
    if (t == 0) {
        float z = 0.f;
        #pragma unroll
        for (int i = 0; i < 8; i++) z += red[i];
        red[0] = z;
    }
    __syncthreads();
    return red[0];
}

__device__ __forceinline__ float gelu_f(float x) {
    float x3 = x * x * x;
    return 0.5f * x * (1.f + tanhf(0.7978845608028654f * (x + 0.044715f * x3)));
}

__device__ __forceinline__ unsigned f2tf32(float f) {
    unsigned r;
    asm("cvt.rna.tf32.f32 %0, %1;" : "=r"(r) : "f"(f));
    return r;
}

// ---------------- LayerNorm ----------------
__global__ __launch_bounds__(256) void ln_kernel(const float* __restrict__ x,
                                                 const float* __restrict__ g,
                                                 const float* __restrict__ b,
                                                 float* __restrict__ out) {
    __shared__ float red[8];
    int row = blockIdx.x;
    const float* xr = x + (size_t)row * DM_;
    int t = threadIdx.x;
    float v[4];
    float s = 0.f;
    #pragma unroll
    for (int i = 0; i < 4; i++) { v[i] = xr[t + i * 256]; s += v[i]; }
    float mean = block_sum(s, red) * (1.f / DM_);
    float s2 = 0.f;
    #pragma unroll
    for (int i = 0; i < 4; i++) { float d = v[i] - mean; s2 += d * d; }
    float var = block_sum(s2, red) * (1.f / DM_);
    float inv = rsqrtf(var + 1e-5f);
    float* orow = out + (size_t)row * DM_;
    #pragma unroll
    for (int i = 0; i < 4; i++) {
        int c = t + i * 256;
        orow[c] = (v[i] - mean) * inv * g[c] + b[c];
    }
}

// ---------------- tf32 tensor-core GEMM: C = act(A@B + bias) + res ----------------
// 128x128 block tile, BK=16, 256 threads = 8 warps (4x2), warp tile 32x64.
// mma.sync.aligned.m16n8k8.row.col.f32.tf32.tf32.f32
// Double-buffered smem with register prefetch.
template<bool BIAS, bool RES, bool GELU_>
__global__ __launch_bounds__(256, 2) void mma_gemm(const float* __restrict__ A,
                                                   const float* __restrict__ B,
                                                   const float* __restrict__ bias,
                                                   const float* __restrict__ res,
                                                   float* __restrict__ C,
                                                   int M, int N, int K) {
    // A tile stored [m][k], pad 20 (conflict-free for fragment reads)
    // B tile stored [k][n], pad 136
    __shared__ unsigned As[2][128][20];
    __shared__ unsigned Bs[2][16][136];

    int tid  = threadIdx.x;
    int lane = tid & 31;
    int wid  = tid >> 5;
    int bm = blockIdx.y * 128, bn = blockIdx.x * 128;
    int wm = wid >> 1, wn = wid & 1;

    float acc[2][8][4];
    #pragma unroll
    for (int fm = 0; fm < 2; fm++)
        #pragma unroll
        for (int fn = 0; fn < 8; fn++)
            #pragma unroll
            for (int i = 0; i < 4; i++) acc[fm][fn][i] = 0.f;

    // gmem load coords
    int ar = tid >> 2, ac = (tid & 3) * 4;     // A: rows ar, ar+64; cols ac..ac+3
    int br = tid >> 5, bc = (tid & 31) * 4;    // B: rows br, br+8;  cols bc..bc+3

    const float* Ap0 = A + (size_t)(bm + ar) * K + ac;
    const float* Ap1 = A + (size_t)(bm + ar + 64) * K + ac;
    const float* Bp0 = B + (size_t)br * N + bn + bc;
    const float* Bp1 = B + (size_t)(br + 8) * N + bn + bc;

    // preload tile 0 into buffer 0
    {
        float4 a0 = *(const float4*)(Ap0);
        float4 a1 = *(const float4*)(Ap1);
        float4 b0 = *(const float4*)(Bp0);
        float4 b1 = *(const float4*)(Bp1);
        *(uint4*)&As[0][ar][ac]      = make_uint4(f2tf32(a0.x), f2tf32(a0.y), f2tf32(a0.z), f2tf32(a0.w));
        *(uint4*)&As[0][ar + 64][ac] = make_uint4(f2tf32(a1.x), f2tf32(a1.y), f2tf32(a1.z), f2tf32(a1.w));
        *(uint4*)&Bs[0][br][bc]      = make_uint4(f2tf32(b0.x), f2tf32(b0.y), f2tf32(b0.z), f2tf32(b0.w));
        *(uint4*)&Bs[0][br + 8][bc]  = make_uint4(f2tf32(b1.x), f2tf32(b1.y), f2tf32(b1.z), f2tf32(b1.w));
    }
    __syncthreads();

    int buf = 0;
    for (int k0 = 0; k0 < K; k0 += 16) {
        bool has_next = (k0 + 16) < K;
        float4 pa0, pa1, pb0, pb1;
        if (has_next) {
            pa0 = *(const float4*)(Ap0 + k0 + 16);
            pa1 = *(const float4*)(Ap1 + k0 + 16);
            pb0 = *(const float4*)(Bp0 + (size_t)(k0 + 16) * N);
            pb1 = *(const float4*)(Bp1 + (size_t)(k0 + 16) * N);
        }

        // compute on current buffer
        #pragma unroll
        for (int s = 0; s < 2; s++) {
            unsigned af[2][4], bf[8][2];
            int kq = s * 8 + (lane & 3);
            int mrow = wm * 32 + (lane >> 2);
            #pragma unroll
            for (int fm = 0; fm < 2; fm++) {
                af[fm][0] = As[buf][mrow + fm * 16][kq];
                af[fm][1] = As[buf][mrow + fm * 16 + 8][kq];
                af[fm][2] = As[buf][mrow + fm * 16][kq + 4];
                af[fm][3] = As[buf][mrow + fm * 16 + 8][kq + 4];
            }
            int ncol = wn * 64 + (lane >> 2);
            #pragma unroll
            for (int fn = 0; fn < 8; fn++) {
                bf[fn][0] = Bs[buf][s * 8 + (lane & 3)][ncol + fn * 8];
                bf[fn][1] = Bs[buf][s * 8 + (lane & 3) + 4][ncol + fn * 8];
            }
            #pragma unroll
            for (int fm = 0; fm < 2; fm++)
                #pragma unroll
                for (int fn = 0; fn < 8; fn++) {
                    asm volatile(
                        "mma.sync.aligned.m16n8k8.row.col.f32.tf32.tf32.f32 "
                        "{%0,%1,%2,%3}, {%4,%5,%6,%7}, {%8,%9}, {%0,%1,%2,%3};\n"
                        : "+f"(acc[fm][fn][0]), "+f"(acc[fm][fn][1]),
                          "+f"(acc[fm][fn][2]), "+f"(acc[fm][fn][3])
                        : "r"(af[fm][0]), "r"(af[fm][1]), "r"(af[fm][2]), "r"(af[fm][3]),
                          "r"(bf[fn][0]), "r"(bf[fn][1]));
                }
        }

        if (has_next) {
            int nb = buf ^ 1;
            *(uint4*)&As[nb][ar][ac]      = make_uint4(f2tf32(pa0.x), f2tf32(pa0.y), f2tf32(pa0.z), f2tf32(pa0.w));
            *(uint4*)&As[nb][ar + 64][ac] = make_uint4(f2tf32(pa1.x), f2tf32(pa1.y), f2tf32(pa1.z), f2tf32(pa1.w));
            *(uint4*)&Bs[nb][br][bc]      = make_uint4(f2tf32(pb0.x), f2tf32(pb0.y), f2tf32(pb0.z), f2tf32(pb0.w));
            *(uint4*)&Bs[nb][br + 8][bc]  = make_uint4(f2tf32(pb1.x), f2tf32(pb1.y), f2tf32(pb1.z), f2tf32(pb1.w));
        }
        __syncthreads();
        buf ^= 1;
    }

    // epilogue
    #pragma unroll
    for (int fm = 0; fm < 2; fm++) {
        int r_lo = bm + wm * 32 + fm * 16 + (lane >> 2);
        #pragma unroll
        for (int fn = 0; fn < 8; fn++) {
            int col = bn + wn * 64 + fn * 8 + 2 * (lane & 3);
            float v0 = acc[fm][fn][0], v1 = acc[fm][fn][1];
            float v2 = acc[fm][fn][2], v3 = acc[fm][fn][3];
            if (BIAS) {
                float b0v = bias[col], b1v = bias[col + 1];
                v0 += b0v; v1 += b1v; v2 += b0v; v3 += b1v;
            }
            if (GELU_) { v0 = gelu_f(v0); v1 = gelu_f(v1); v2 = gelu_f(v2); v3 = gelu_f(v3); }
            if (RES) {
                float2 r0 = *(const float2*)(res + (size_t)r_lo * N + col);
                float2 r1 = *(const float2*)(res + (size_t)(r_lo + 8) * N + col);
                v0 += r0.x; v1 += r0.y; v2 += r1.x; v3 += r1.y;
            }
            *(float2*)(C + (size_t)r_lo * N + col)       = make_float2(v0, v1);
            *(float2*)(C + (size_t)(r_lo + 8) * N + col) = make_float2(v2, v3);
        }
    }
}

// ---------------- banded attention (flash-style online softmax) ----------------
__global__ __launch_bounds__(256) void attn_kernel(const float* __restrict__ Q,
                                                   const float* __restrict__ Kb,
                                                   const float* __restrict__ Vb,
                                                   const float* __restrict__ rel_emb,
                                                   float* __restrict__ O) {
    __shared__ float qs[BS_ * 65];
    __shared__ float kv[BS_ * 65];
    __shared__ float red1[4 * 64];
    __shared__ float red2[4 * 64];
    __shared__ float bias_s[258];
    __shared__ float invl_s[64];

    int n = blockIdx.x, h = blockIdx.y;
    int tid = threadIdx.x;
    int si = tid & 63, jc = tid >> 6;

    for (int t = tid; t < BS_ * DH_; t += 256) {
        int i = t >> 6, d = t & 63;
        qs[i * 65 + d] = Q[(size_t)(n * BS_ + i) * DM_ + h * DH_ + d] * 0.125f;
    }
    for (int t = tid; t < 258; t += 256) bias_s[t] = rel_emb[t * H_ + h];

    float acc[64];
    #pragma unroll
    for (int d = 0; d < 64; d++) acc[d] = 0.f;
    float m_run = -1e30f, l_run = 0.f;

    int w0 = (n >= W_ - 1) ? 0 : (W_ - 1 - n);
    for (int w = w0; w < W_; w++) {
        int sb = n - (W_ - 1) + w;
        __syncthreads();
        for (int t = tid; t < BS_ * DH_; t += 256) {
            int j = t >> 6, d = t & 63;
            kv[j * 65 + d] = Kb[(size_t)(sb * BS_ + j) * DM_ + h * DH_ + d];
        }
        __syncthreads();

        float s[16];
        #pragma unroll
        for (int jj = 0; jj < 16; jj++) s[jj] = 0.f;
        #pragma unroll 8
        for (int d = 0; d < 64; d++) {
            float qv = qs[si * 65 + d];
            #pragma unroll
            for (int jj = 0; jj < 16; jj++)
                s[jj] += qv * kv[(jc * 16 + jj) * 65 + d];
        }

        float mx = -1e30f;
        #pragma unroll
        for (int jj = 0; jj < 16; jj++) {
            int j = jc * 16 + jj;
            int delta = (W_ - 1 - w) * 64 + si - j;
            int idx = min(delta, 256) + 1;
            idx = max(idx, 0);
            float val = s[jj] + bias_s[idx];
            if (w == W_ - 1 && j > si) val = -1e30f;
            s[jj] = val;
            mx = fmaxf(mx, val);
        }
        red1[jc * 64 + si] = mx;
        __syncthreads();

        float m_new = m_run;
        #pragma unroll
        for (int c = 0; c < 4; c++) m_new = fmaxf(m_new, red1[c * 64 + si]);
        float lsum = 0.f;
        #pragma unroll
        for (int jj = 0; jj < 16; jj++) { s[jj] = __expf(s[jj] - m_new); lsum += s[jj]; }
        red2[jc * 64 + si] = lsum;

        for (int t = tid; t < BS_ * DH_; t += 256) {
            int j = t >> 6, d = t & 63;
            kv[j * 65 + d] = Vb[(size_t)(sb * BS_ + j) * DM_ + h * DH_ + d];
        }
        __syncthreads();

        float rs = 0.f;
        #pragma unroll
        for (int c = 0; c < 4; c++) rs += red2[c * 64 + si];
        float scale = __expf(m_run - m_new);
        l_run = l_run * scale + rs;
        m_run = m_new;
        #pragma unroll
        for (int d = 0; d < 64; d++) acc[d] *= scale;
        #pragma unroll
        for (int jj = 0; jj < 16; jj++) {
            float p = s[jj];
            int j = jc * 16 + jj;
            #pragma unroll
            for (int d = 0; d < 64; d++)
                acc[d] += p * kv[j * 65 + d];
        }
    }

    if (jc == 0) invl_s[si] = 1.f / l_run;
    __syncthreads();
    #pragma unroll
    for (int c = 0; c < 4; c++) {
        if (jc == c) {
            if (c == 0) {
                #pragma unroll
                for (int d = 0; d < 64; d++) kv[si * 65 + d] = acc[d];
            } else {
                #pragma unroll
                for (int d = 0; d < 64; d++) kv[si * 65 + d] += acc[d];
            }
        }
        __syncthreads();
    }
    for (int t = tid; t < BS_ * DH_; t += 256) {
        int i = t >> 6, d = t & 63;
        O[(size_t)(n * BS_ + i) * DM_ + h * DH_ + d] = kv[i * 65 + d] * invl_s[i];
    }
}

// ---------------- launch ----------------
extern "C" void kernel_launch(void* const* d_in, const int* in_sizes, int n_in,
                              void* d_out, int out_size) {
    (void)in_sizes; (void)n_in; (void)out_size;
    const float* x      = (const float*)d_in[0];
    const float* Wq     = (const float*)d_in[1];
    const float* Wk     = (const float*)d_in[2];
    const float* Wv     = (const float*)d_in[3];
    const float* Wo     = (const float*)d_in[4];
    const float* rel    = (const float*)d_in[5];
    const float* ln1g   = (const float*)d_in[6];
    const float* ln1b   = (const float*)d_in[7];
    const float* ln2g   = (const float*)d_in[8];
    const float* ln2b   = (const float*)d_in[9];
    const float* W1     = (const float*)d_in[10];
    const float* b1     = (const float*)d_in[11];
    const float* W2     = (const float*)d_in[12];
    const float* b2     = (const float*)d_in[13];
    float* out = (float*)d_out;

    float *Hb, *Qb, *Kb, *Vb, *Ob, *X1, *Gb;
    cudaGetSymbolAddress((void**)&Hb, g_H);
    cudaGetSymbolAddress((void**)&Qb, g_Q);
    cudaGetSymbolAddress((void**)&Kb, g_K);
    cudaGetSymbolAddress((void**)&Vb, g_V);
    cudaGetSymbolAddress((void**)&Ob, g_O);
    cudaGetSymbolAddress((void**)&X1, g_X1);
    cudaGetSymbolAddress((void**)&Gb, g_G);

    // 1. h = LN1(x)
    ln_kernel<<<L_, 256>>>(x, ln1g, ln1b, Hb);

    // 2. Q, K, V
    dim3 g1(DM_ / 128, L_ / 128);
    mma_gemm<false, false, false><<<g1, 256>>>(Hb, Wq, nullptr, nullptr, Qb, L_, DM_, DM_);
    mma_gemm<false, false, false><<<g1, 256>>>(Hb, Wk, nullptr, nullptr, Kb, L_, DM_, DM_);
    mma_gemm<false, false, false><<<g1, 256>>>(Hb, Wv, nullptr, nullptr, Vb, L_, DM_, DM_);

    // 3. banded attention
    attn_kernel<<<dim3(NB_, H_), 256>>>(Qb, Kb, Vb, rel, Ob);

    // 4. x1 = x + O @ Wo
    mma_gemm<false, true, false><<<g1, 256>>>(Ob, Wo, nullptr, x, X1, L_, DM_, DM_);

    // 5. h2 = LN2(x1)  (reuse g_H)
    ln_kernel<<<L_, 256>>>(X1, ln2g, ln2b, Hb);

    // 6. G = gelu(h2 @ W1 + b1)
    mma_gemm<true, false, true><<<dim3(DFF_ / 128, L_ / 128), 256>>>(Hb, W1, b1, nullptr, Gb, L_, DFF_, DM_);

    // 7. out = x1 + G @ W2 + b2
    mma_gemm<true, true, false><<<g1, 256>>>(Gb, W2, b2, X1, out, L_, DM_, DFF_);
}

// round 3
// speedup vs baseline: 3.6498x; 1.8403x over previous
#include <cuda_runtime.h>
#include <math.h>

#define L_   4096
#define DM_  1024
#define H_   16
#define DH_  64
#define BS_  64
#define W_   16
#define NB_  64
#define DFF_ 4096

// ---------------- scratch (static __device__ arrays; no allocations) ----------------
__device__ float g_H [L_ * DM_];   // LN1 output, reused for LN2 output
__device__ float g_Q [L_ * DM_];
__device__ float g_K [L_ * DM_];
__device__ float g_V [L_ * DM_];
__device__ float g_O [L_ * DM_];   // attention output (pre-Wo)
__device__ float g_X1[L_ * DM_];   // x + attn@Wo
__device__ float g_G [L_ * DFF_];  // gelu(h2@W1+b1)

// ---------------- helpers ----------------
__device__ __forceinline__ float block_sum(float val, float* red) {
    int t = threadIdx.x;
    #pragma unroll
    for (int o = 16; o > 0; o >>= 1) val += __shfl_xor_sync(0xffffffffu, val, o);
    __syncthreads();
    if ((t & 31) == 0) red[t >> 5] = val;
    __syncthreads();
    if (t == 0) {
        float z = 0.f;
        #pragma unroll
        for (int i = 0; i < 8; i++) z += red[i];
        red[0] = z;
    }
    __syncthreads();
    return red[0];
}

__device__ __forceinline__ float gelu_f(float x) {
    float x3 = x * x * x;
    return 0.5f * x * (1.f + tanhf(0.7978845608028654f * (x + 0.044715f * x3)));
}

__device__ __forceinline__ unsigned f2tf32(float f) {
    unsigned r;
    asm("cvt.rna.tf32.f32 %0, %1;" : "=r"(r) : "f"(f));
    return r;
}

__device__ __forceinline__ void mma_tf32(float* d, const unsigned* a, unsigned b0, unsigned b1) {
    asm volatile(
        "mma.sync.aligned.m16n8k8.row.col.f32.tf32.tf32.f32 "
        "{%0,%1,%2,%3}, {%4,%5,%6,%7}, {%8,%9}, {%0,%1,%2,%3};\n"
        : "+f"(d[0]), "+f"(d[1]), "+f"(d[2]), "+f"(d[3])
        : "r"(a[0]), "r"(a[1]), "r"(a[2]), "r"(a[3]), "r"(b0), "r"(b1));
}

// ---------------- LayerNorm ----------------
__global__ __launch_bounds__(256) void ln_kernel(const float* __restrict__ x,
                                                 const float* __restrict__ g,
                                                 const float* __restrict__ b,
                                                 float* __restrict__ out) {
    __shared__ float red[8];
    int row = blockIdx.x;
    const float* xr = x + (size_t)row * DM_;
    int t = threadIdx.x;
    float v[4];
    float s = 0.f;
    #pragma unroll
    for (int i = 0; i < 4; i++) { v[i] = xr[t + i * 256]; s += v[i]; }
    float mean = block_sum(s, red) * (1.f / DM_);
    float s2 = 0.f;
    #pragma unroll
    for (int i = 0; i < 4; i++) { float d = v[i] - mean; s2 += d * d; }
    float var = block_sum(s2, red) * (1.f / DM_);
    float inv = rsqrtf(var + 1e-5f);
    float* orow = out + (size_t)row * DM_;
    #pragma unroll
    for (int i = 0; i < 4; i++) {
        int c = t + i * 256;
        orow[c] = (v[i] - mean) * inv * g[c] + b[c];
    }
}

// ---------------- tf32 tensor-core GEMM: C = act(A@B + bias) + res ----------------
template<bool BIAS, bool RES, bool GELU_>
__global__ __launch_bounds__(256, 2) void mma_gemm(const float* __restrict__ A,
                                                   const float* __restrict__ B,
                                                   const float* __restrict__ bias,
                                                   const float* __restrict__ res,
                                                   float* __restrict__ C,
                                                   int M, int N, int K) {
    __shared__ unsigned As[2][128][20];
    __shared__ unsigned Bs[2][16][136];

    int tid  = threadIdx.x;
    int lane = tid & 31;
    int wid  = tid >> 5;
    int bm = blockIdx.y * 128, bn = blockIdx.x * 128;
    int wm = wid >> 1, wn = wid & 1;

    float acc[2][8][4];
    #pragma unroll
    for (int fm = 0; fm < 2; fm++)
        #pragma unroll
        for (int fn = 0; fn < 8; fn++)
            #pragma unroll
            for (int i = 0; i < 4; i++) acc[fm][fn][i] = 0.f;

    int ar = tid >> 2, ac = (tid & 3) * 4;
    int br = tid >> 5, bc = (tid & 31) * 4;

    const float* Ap0 = A + (size_t)(bm + ar) * K + ac;
    const float* Ap1 = A + (size_t)(bm + ar + 64) * K + ac;
    const float* Bp0 = B + (size_t)br * N + bn + bc;
    const float* Bp1 = B + (size_t)(br + 8) * N + bn + bc;

    {
        float4 a0 = *(const float4*)(Ap0);
        float4 a1 = *(const float4*)(Ap1);
        float4 b0 = *(const float4*)(Bp0);
        float4 b1 = *(const float4*)(Bp1);
        *(uint4*)&As[0][ar][ac]      = make_uint4(f2tf32(a0.x), f2tf32(a0.y), f2tf32(a0.z), f2tf32(a0.w));
        *(uint4*)&As[0][ar + 64][ac] = make_uint4(f2tf32(a1.x), f2tf32(a1.y), f2tf32(a1.z), f2tf32(a1.w));
        *(uint4*)&Bs[0][br][bc]      = make_uint4(f2tf32(b0.x), f2tf32(b0.y), f2tf32(b0.z), f2tf32(b0.w));
        *(uint4*)&Bs[0][br + 8][bc]  = make_uint4(f2tf32(b1.x), f2tf32(b1.y), f2tf32(b1.z), f2tf32(b1.w));
    }
    __syncthreads();

    int buf = 0;
    for (int k0 = 0; k0 < K; k0 += 16) {
        bool has_next = (k0 + 16) < K;
        float4 pa0, pa1, pb0, pb1;
        if (has_next) {
            pa0 = *(const float4*)(Ap0 + k0 + 16);
            pa1 = *(const float4*)(Ap1 + k0 + 16);
            pb0 = *(const float4*)(Bp0 + (size_t)(k0 + 16) * N);
            pb1 = *(const float4*)(Bp1 + (size_t)(k0 + 16) * N);
        }

        #pragma unroll
        for (int s = 0; s < 2; s++) {
            unsigned af[2][4], bf[8][2];
            int kq = s * 8 + (lane & 3);
            int mrow = wm * 32 + (lane >> 2);
            #pragma unroll
            for (int fm = 0; fm < 2; fm++) {
                af[fm][0] = As[buf][mrow + fm * 16][kq];
                af[fm][1] = As[buf][mrow + fm * 16 + 8][kq];
                af[fm][2] = As[buf][mrow + fm * 16][kq + 4];
                af[fm][3] = As[buf][mrow + fm * 16 + 8][kq + 4];
            }
            int ncol = wn * 64 + (lane >> 2);
            #pragma unroll
            for (int fn = 0; fn < 8; fn++) {
                bf[fn][0] = Bs[buf][s * 8 + (lane & 3)][ncol + fn * 8];
                bf[fn][1] = Bs[buf][s * 8 + (lane & 3) + 4][ncol + fn * 8];
            }
            #pragma unroll
            for (int fm = 0; fm < 2; fm++)
                #pragma unroll
                for (int fn = 0; fn < 8; fn++)
                    mma_tf32(acc[fm][fn], af[fm], bf[fn][0], bf[fn][1]);
        }

        if (has_next) {
            int nb = buf ^ 1;
            *(uint4*)&As[nb][ar][ac]      = make_uint4(f2tf32(pa0.x), f2tf32(pa0.y), f2tf32(pa0.z), f2tf32(pa0.w));
            *(uint4*)&As[nb][ar + 64][ac] = make_uint4(f2tf32(pa1.x), f2tf32(pa1.y), f2tf32(pa1.z), f2tf32(pa1.w));
            *(uint4*)&Bs[nb][br][bc]      = make_uint4(f2tf32(pb0.x), f2tf32(pb0.y), f2tf32(pb0.z), f2tf32(pb0.w));
            *(uint4*)&Bs[nb][br + 8][bc]  = make_uint4(f2tf32(pb1.x), f2tf32(pb1.y), f2tf32(pb1.z), f2tf32(pb1.w));
        }
        __syncthreads();
        buf ^= 1;
    }

    #pragma unroll
    for (int fm = 0; fm < 2; fm++) {
        int r_lo = bm + wm * 32 + fm * 16 + (lane >> 2);
        #pragma unroll
        for (int fn = 0; fn < 8; fn++) {
            int col = bn + wn * 64 + fn * 8 + 2 * (lane & 3);
            float v0 = acc[fm][fn][0], v1 = acc[fm][fn][1];
            float v2 = acc[fm][fn][2], v3 = acc[fm][fn][3];
            if (BIAS) {
                float b0v = bias[col], b1v = bias[col + 1];
                v0 += b0v; v1 += b1v; v2 += b0v; v3 += b1v;
            }
            if (GELU_) { v0 = gelu_f(v0); v1 = gelu_f(v1); v2 = gelu_f(v2); v3 = gelu_f(v3); }
            if (RES) {
                float2 r0 = *(const float2*)(res + (size_t)r_lo * N + col);
                float2 r1 = *(const float2*)(res + (size_t)(r_lo + 8) * N + col);
                v0 += r0.x; v1 += r0.y; v2 += r1.x; v3 += r1.y;
            }
            *(float2*)(C + (size_t)r_lo * N + col)       = make_float2(v0, v1);
            *(float2*)(C + (size_t)(r_lo + 8) * N + col) = make_float2(v2, v3);
        }
    }
}

// ---------------- banded attention, tensor-core (tf32 mma + register flash softmax) ----
// grid (NB, H), 128 threads = 4 warps; warp w owns query rows [w*16, w*16+16).
// Smem: Qs[64][68] (reused as Ps), Ks[64][68], Vs[64][72], bias[258].
#define QP_PAD 68
#define V_PAD  72
#define ATTN_SMEM_WORDS (2 * 64 * QP_PAD + 64 * V_PAD + 258)

__global__ __launch_bounds__(128) void attn_mma(const float* __restrict__ Q,
                                                const float* __restrict__ Kb,
                                                const float* __restrict__ Vb,
                                                const float* __restrict__ rel_emb,
                                                float* __restrict__ O) {
    extern __shared__ unsigned smem_u[];
    unsigned (*Qs)[QP_PAD] = (unsigned(*)[QP_PAD])smem_u;            // also Ps
    unsigned (*Ks)[QP_PAD] = (unsigned(*)[QP_PAD])(smem_u + 64 * QP_PAD);
    unsigned (*Vs)[V_PAD]  = (unsigned(*)[V_PAD]) (smem_u + 2 * 64 * QP_PAD);
    float* bias_s = (float*)(smem_u + 2 * 64 * QP_PAD + 64 * V_PAD);

    int n = blockIdx.x, h = blockIdx.y;
    int tid = threadIdx.x, lane = tid & 31, wid = tid >> 5;
    int r = lane >> 2, c = lane & 3;

    // load Q (scaled) as tf32
    for (int t = tid; t < 1024; t += 128) {
        int i = t >> 4, d4 = (t & 15) * 4;
        float4 q = *(const float4*)(Q + (size_t)(n * 64 + i) * DM_ + h * 64 + d4);
        Qs[i][d4 + 0] = f2tf32(q.x * 0.125f);
        Qs[i][d4 + 1] = f2tf32(q.y * 0.125f);
        Qs[i][d4 + 2] = f2tf32(q.z * 0.125f);
        Qs[i][d4 + 3] = f2tf32(q.w * 0.125f);
    }
    for (int t = tid; t < 258; t += 128) bias_s[t] = rel_emb[t * H_ + h];
    __syncthreads();

    // Q fragments into registers (row slice wid*16 .. +16)
    unsigned qf[8][4];
    int row0 = wid * 16 + r;
    #pragma unroll
    for (int kk = 0; kk < 8; kk++) {
        qf[kk][0] = Qs[row0][kk * 8 + c];
        qf[kk][1] = Qs[row0 + 8][kk * 8 + c];
        qf[kk][2] = Qs[row0][kk * 8 + c + 4];
        qf[kk][3] = Qs[row0 + 8][kk * 8 + c + 4];
    }

    float of[8][4];
    #pragma unroll
    for (int f = 0; f < 8; f++)
        #pragma unroll
        for (int e = 0; e < 4; e++) of[f][e] = 0.f;
    float m0 = -1e30f, m1 = -1e30f, l0 = 0.f, l1 = 0.f;

    int w0 = (n >= W_ - 1) ? 0 : (W_ - 1 - n);
    for (int w = w0; w < W_; w++) {
        int sb = n - (W_ - 1) + w;
        __syncthreads();   // prev window's Ks/Vs reads (and Qs-frag reads on first iter) done
        for (int t = tid; t < 1024; t += 128) {
            int j = t >> 4, d4 = (t & 15) * 4;
            const float* kp = Kb + (size_t)(sb * 64 + j) * DM_ + h * 64 + d4;
            const float* vp = Vb + (size_t)(sb * 64 + j) * DM_ + h * 64 + d4;
            float4 kx = *(const float4*)kp;
            float4 vx = *(const float4*)vp;
            Ks[j][d4 + 0] = f2tf32(kx.x); Ks[j][d4 + 1] = f2tf32(kx.y);
            Ks[j][d4 + 2] = f2tf32(kx.z); Ks[j][d4 + 3] = f2tf32(kx.w);
            Vs[j][d4 + 0] = f2tf32(vx.x); Vs[j][d4 + 1] = f2tf32(vx.y);
            Vs[j][d4 + 2] = f2tf32(vx.z); Vs[j][d4 + 3] = f2tf32(vx.w);
        }
        __syncthreads();

        // S = Q @ K^T  (per warp: rows row0-slice, all 64 cols)
        float sf[8][4];
        #pragma unroll
        for (int f = 0; f < 8; f++)
            #pragma unroll
            for (int e = 0; e < 4; e++) sf[f][e] = 0.f;
        #pragma unroll
        for (int kk = 0; kk < 8; kk++) {
            #pragma unroll
            for (int f = 0; f < 8; f++) {
                unsigned b0 = Ks[f * 8 + r][kk * 8 + c];
                unsigned b1 = Ks[f * 8 + r][kk * 8 + c + 4];
                mma_tf32(sf[f], qf[kk], b0, b1);
            }
        }

        // bias + mask + register flash softmax
        int base = (W_ - 1 - w) * 64;
        bool last = (w == W_ - 1);
        float mx0 = -1e30f, mx1 = -1e30f;
        #pragma unroll
        for (int f = 0; f < 8; f++) {
            #pragma unroll
            for (int e = 0; e < 2; e++) {
                int j = f * 8 + 2 * c + e;
                int d0 = base + row0 - j;
                int d1 = d0 + 8;
                float v0 = sf[f][e]     + bias_s[max(min(d0, 256) + 1, 0)];
                float v1 = sf[f][e + 2] + bias_s[max(min(d1, 256) + 1, 0)];
                if (last && d0 < 0) v0 = -1e30f;
                if (last && d1 < 0) v1 = -1e30f;
                sf[f][e] = v0; sf[f][e + 2] = v1;
                mx0 = fmaxf(mx0, v0); mx1 = fmaxf(mx1, v1);
            }
        }
        mx0 = fmaxf(mx0, __shfl_xor_sync(0xffffffffu, mx0, 1));
        mx0 = fmaxf(mx0, __shfl_xor_sync(0xffffffffu, mx0, 2));
        mx1 = fmaxf(mx1, __shfl_xor_sync(0xffffffffu, mx1, 1));
        mx1 = fmaxf(mx1, __shfl_xor_sync(0xffffffffu, mx1, 2));
        float mn0 = fmaxf(m0, mx0), mn1 = fmaxf(m1, mx1);
        float sc0 = __expf(m0 - mn0), sc1 = __expf(m1 - mn1);
        m0 = mn0; m1 = mn1;

        float s0 = 0.f, s1 = 0.f;
        #pragma unroll
        for (int f = 0; f < 8; f++) {
            #pragma unroll
            for (int e = 0; e < 2; e++) {
                int col = f * 8 + 2 * c + e;
                float p0 = __expf(sf[f][e]     - mn0);
                float p1 = __expf(sf[f][e + 2] - mn1);
                s0 += p0; s1 += p1;
                Qs[row0][col]     = f2tf32(p0);   // Ps (warp-private rows)
                Qs[row0 + 8][col] = f2tf32(p1);
            }
        }
        s0 += __shfl_xor_sync(0xffffffffu, s0, 1);
        s0 += __shfl_xor_sync(0xffffffffu, s0, 2);
        s1 += __shfl_xor_sync(0xffffffffu, s1, 1);
        s1 += __shfl_xor_sync(0xffffffffu, s1, 2);
        l0 = l0 * sc0 + s0;
        l1 = l1 * sc1 + s1;
        #pragma unroll
        for (int f = 0; f < 8; f++) {
            of[f][0] *= sc0; of[f][1] *= sc0;
            of[f][2] *= sc1; of[f][3] *= sc1;
        }
        __syncwarp();

        // O += P @ V
        #pragma unroll
        for (int kk = 0; kk < 8; kk++) {
            unsigned pa[4];
            pa[0] = Qs[row0][kk * 8 + c];
            pa[1] = Qs[row0 + 8][kk * 8 + c];
            pa[2] = Qs[row0][kk * 8 + c + 4];
            pa[3] = Qs[row0 + 8][kk * 8 + c + 4];
            #pragma unroll
            for (int f = 0; f < 8; f++) {
                unsigned b0 = Vs[kk * 8 + c][f * 8 + r];
                unsigned b1 = Vs[kk * 8 + c + 4][f * 8 + r];
                mma_tf32(of[f], pa, b0, b1);
            }
        }
    }

    float invl0 = 1.f / l0, invl1 = 1.f / l1;
    #pragma unroll
    for (int f = 0; f < 8; f++) {
        int col = f * 8 + 2 * c;
        *(float2*)(O + (size_t)(n * 64 + row0) * DM_ + h * 64 + col) =
            make_float2(of[f][0] * invl0, of[f][1] * invl0);
        *(float2*)(O + (size_t)(n * 64 + row0 + 8) * DM_ + h * 64 + col) =
            make_float2(of[f][2] * invl1, of[f][3] * invl1);
    }
}

// ---------------- launch ----------------
extern "C" void kernel_launch(void* const* d_in, const int* in_sizes, int n_in,
                              void* d_out, int out_size) {
    (void)in_sizes; (void)n_in; (void)out_size;
    const float* x      = (const float*)d_in[0];
    const float* Wq     = (const float*)d_in[1];
    const float* Wk     = (const float*)d_in[2];
    const float* Wv     = (const float*)d_in[3];
    const float* Wo     = (const float*)d_in[4];
    const float* rel    = (const float*)d_in[5];
    const float* ln1g   = (const float*)d_in[6];
    const float* ln1b   = (const float*)d_in[7];
    const float* ln2g   = (const float*)d_in[8];
    const float* ln2b   = (const float*)d_in[9];
    const float* W1     = (const float*)d_in[10];
    const float* b1     = (const float*)d_in[11];
    const float* W2     = (const float*)d_in[12];
    const float* b2     = (const float*)d_in[13];
    float* out = (float*)d_out;

    float *Hb, *Qb, *Kb, *Vb, *Ob, *X1, *Gb;
    cudaGetSymbolAddress((void**)&Hb, g_H);
    cudaGetSymbolAddress((void**)&Qb, g_Q);
    cudaGetSymbolAddress((void**)&Kb, g_K);
    cudaGetSymbolAddress((void**)&Vb, g_V);
    cudaGetSymbolAddress((void**)&Ob, g_O);
    cudaGetSymbolAddress((void**)&X1, g_X1);
    cudaGetSymbolAddress((void**)&Gb, g_G);

    const int attn_smem = ATTN_SMEM_WORDS * 4;
    cudaFuncSetAttribute(attn_mma, cudaFuncAttributeMaxDynamicSharedMemorySize, attn_smem);

    // 1. h = LN1(x)
    ln_kernel<<<L_, 256>>>(x, ln1g, ln1b, Hb);

    // 2. Q, K, V
    dim3 g1(DM_ / 128, L_ / 128);
    mma_gemm<false, false, false><<<g1, 256>>>(Hb, Wq, nullptr, nullptr, Qb, L_, DM_, DM_);
    mma_gemm<false, false, false><<<g1, 256>>>(Hb, Wk, nullptr, nullptr, Kb, L_, DM_, DM_);
    mma_gemm<false, false, false><<<g1, 256>>>(Hb, Wv, nullptr, nullptr, Vb, L_, DM_, DM_);

    // 3. banded attention (tensor cores)
    attn_mma<<<dim3(NB_, H_), 128, attn_smem>>>(Qb, Kb, Vb, rel, Ob);

    // 4. x1 = x + O @ Wo
    mma_gemm<false, true, false><<<g1, 256>>>(Ob, Wo, nullptr, x, X1, L_, DM_, DM_);

    // 5. h2 = LN2(x1)
    ln_kernel<<<L_, 256>>>(X1, ln2g, ln2b, Hb);

    // 6. G = gelu(h2 @ W1 + b1)
    mma_gemm<true, false, true><<<dim3(DFF_ / 128, L_ / 128), 256>>>(Hb, W1, b1, nullptr, Gb, L_, DFF_, DM_);

    // 7. out = x1 + G @ W2 + b2
    mma_gemm<true, true, false><<<g1, 256>>>(Gb, W2, b2, X1, out, L_, DM_, DFF_);
}

// round 6
// speedup vs baseline: 4.2348x; 1.1603x over previous
#include <cuda_runtime.h>
#include <stdint.h>
#include <math.h>

#define L_   4096
#define DM_  1024
#define H_   16
#define DH_  64
#define BS_  64
#define W_   16
#define NB_  64
#define DFF_ 4096

// ---------------- scratch (static __device__ arrays; no allocations) ----------------
__device__ float g_H [L_ * DM_];   // LN output (tf32-rounded)
__device__ float g_Q [L_ * DM_];
__device__ float g_K [L_ * DM_];
__device__ float g_V [L_ * DM_];
__device__ float g_O [L_ * DM_];   // attention output (tf32-rounded)
__device__ float g_X1[L_ * DM_];   // x + attn@Wo
__device__ float g_G [L_ * DFF_];  // gelu(h2@W1+b1) (tf32-rounded)
// tf32-rounded weights (same [K][N] layout)
__device__ float g_WqR[DM_ * DM_];
__device__ float g_WkR[DM_ * DM_];
__device__ float g_WvR[DM_ * DM_];
__device__ float g_WoR[DM_ * DM_];
__device__ float g_W1R[DM_ * DFF_];
__device__ float g_W2R[DFF_ * DM_];

// ---------------- small helpers ----------------
__device__ __forceinline__ float block_sum(float val, float* red) {
    int t = threadIdx.x;
    #pragma unroll
    for (int o = 16; o > 0; o >>= 1) val += __shfl_xor_sync(0xffffffffu, val, o);
    __syncthreads();
    if ((t & 31) == 0) red[t >> 5] = val;
    __syncthreads();
    if (t == 0) {
        float z = 0.f;
        #pragma unroll
        for (int i = 0; i < 8; i++) z += red[i];
        red[0] = z;
    }
    __syncthreads();
    return red[0];
}

__device__ __forceinline__ float gelu_f(float x) {
    float x3 = x * x * x;
    return 0.5f * x * (1.f + tanhf(0.7978845608028654f * (x + 0.044715f * x3)));
}

__device__ __forceinline__ unsigned f2tf32(float f) {
    unsigned r;
    asm("cvt.rna.tf32.f32 %0, %1;" : "=r"(r) : "f"(f));
    return r;
}
__device__ __forceinline__ float round_tf32(float f) {
    return __uint_as_float(f2tf32(f));
}

__device__ __forceinline__ void mma_tf32(float* d, const unsigned* a, unsigned b0, unsigned b1) {
    asm volatile(
        "mma.sync.aligned.m16n8k8.row.col.f32.tf32.tf32.f32 "
        "{%0,%1,%2,%3}, {%4,%5,%6,%7}, {%8,%9}, {%0,%1,%2,%3};\n"
        : "+f"(d[0]), "+f"(d[1]), "+f"(d[2]), "+f"(d[3])
        : "r"(a[0]), "r"(a[1]), "r"(a[2]), "r"(a[3]), "r"(b0), "r"(b1));
}

__device__ __forceinline__ uint32_t s2u(const void* p) {
    return (uint32_t)__cvta_generic_to_shared(p);
}

__device__ __forceinline__ void cp16(uint32_t dst, const void* src) {
    asm volatile("cp.async.cg.shared.global [%0], [%1], 16;" :: "r"(dst), "l"(src));
}

// ---------------- LayerNorm (writes tf32-rounded output) ----------------
__global__ __launch_bounds__(256) void ln_kernel(const float* __restrict__ x,
                                                 const float* __restrict__ g,
                                                 const float* __restrict__ b,
                                                 float* __restrict__ out) {
    __shared__ float red[8];
    int row = blockIdx.x;
    const float* xr = x + (size_t)row * DM_;
    int t = threadIdx.x;
    float v[4];
    float s = 0.f;
    #pragma unroll
    for (int i = 0; i < 4; i++) { v[i] = xr[t + i * 256]; s += v[i]; }
    float mean = block_sum(s, red) * (1.f / DM_);
    float s2 = 0.f;
    #pragma unroll
    for (int i = 0; i < 4; i++) { float d = v[i] - mean; s2 += d * d; }
    float var = block_sum(s2, red) * (1.f / DM_);
    float inv = rsqrtf(var + 1e-5f);
    float* orow = out + (size_t)row * DM_;
    #pragma unroll
    for (int i = 0; i < 4; i++) {
        int c = t + i * 256;
        orow[c] = round_tf32((v[i] - mean) * inv * g[c] + b[c]);
    }
}

// ---------------- elementwise tf32 round: W -> WR ----------------
__global__ __launch_bounds__(256) void round_w(const float* __restrict__ Wm,
                                               float* __restrict__ WR, int n) {
    int i = (blockIdx.x * 256 + threadIdx.x) * 4;
    if (i < n) {
        float4 v = *(const float4*)(Wm + i);
        *(float4*)(WR + i) = make_float4(round_tf32(v.x), round_tf32(v.y),
                                         round_tf32(v.z), round_tf32(v.w));
    }
}

// ---------------- cp.async pipelined tf32 mma GEMM ----------------
// C = act(A @ B + bias) + res.  A[M][K], B[K][N] both tf32-pre-rounded.
// BM=BN=128, BK=32; 256 threads = 8 warps (4x2 of 32x64 warp tiles).
// 3 smem buffers, 2 cp.async groups in flight, 1 __syncthreads per BK iter.
// blockIdx.z selects among up to 3 (B, C) pairs (QKV fusion).
#define AS_WORDS (128 * 36)
#define BS_WORDS (32 * 136)
#define STAGE_BYTES ((AS_WORDS + BS_WORDS) * 4)
#define PIPE_SMEM (3 * STAGE_BYTES)

template<bool BIAS, bool RES, bool GELU_, bool ROUND>
__global__ __launch_bounds__(256, 2) void mma_gemm_pipe(
        const float* __restrict__ A,
        const float* __restrict__ B0, const float* __restrict__ B1, const float* __restrict__ B2,
        float* __restrict__ C0, float* __restrict__ C1, float* __restrict__ C2,
        const float* __restrict__ bias,
        const float* __restrict__ res,
        int M, int N, int K) {
    extern __shared__ unsigned smem_u[];
    uint32_t sb = s2u(smem_u);

    int tid  = threadIdx.x;
    int lane = tid & 31;
    int wid  = tid >> 5;
    int bm = blockIdx.y * 128, bn = blockIdx.x * 128;
    int wm = wid >> 1, wn = wid & 1;
    int r = lane >> 2, c = lane & 3;

    const float* B = (blockIdx.z == 0) ? B0 : (blockIdx.z == 1) ? B1 : B2;
    float*       C = (blockIdx.z == 0) ? C0 : (blockIdx.z == 1) ? C1 : C2;

    const float* Ab = A + (size_t)bm * K;
    const float* Bb = B + bn;

    float acc[2][8][4];
    #pragma unroll
    for (int fm = 0; fm < 2; fm++)
        #pragma unroll
        for (int fn = 0; fn < 8; fn++)
            #pragma unroll
            for (int i = 0; i < 4; i++) acc[fm][fn][i] = 0.f;

    // per-thread load coords
    int a_row = tid >> 1, a_kq = (tid & 1) * 16;       // 4x cp16: rows a_row, cols a_kq..a_kq+12 step 4? no:
    // A tile 128x32: 1024 float4 / 256 thr = 4 each: idx = p*256+tid -> row=idx>>3, kq=(idx&7)*4
    // B tile 32x128: idx -> row=idx>>5, nq=(idx&31)*4
    (void)a_row; (void)a_kq;

    int NIT = K >> 5;

    auto issue = [&](int it) {
        uint32_t base = sb + (uint32_t)(it % 3) * STAGE_BYTES;
        int k0 = it << 5;
        #pragma unroll
        for (int p = 0; p < 4; p++) {
            int idx = p * 256 + tid;
            int row = idx >> 3, kq = (idx & 7) * 4;
            cp16(base + (uint32_t)(row * 36 + kq) * 4, Ab + (size_t)row * K + k0 + kq);
        }
        #pragma unroll
        for (int p = 0; p < 4; p++) {
            int idx = p * 256 + tid;
            int row = idx >> 5, nq = (idx & 31) * 4;
            cp16(base + (uint32_t)(AS_WORDS + row * 136 + nq) * 4,
                 Bb + (size_t)(k0 + row) * N + nq);
        }
        asm volatile("cp.async.commit_group;" ::: "memory");
    };

    // prologue: 2 stages in flight
    issue(0);
    issue(1);

    for (int it = 0; it < NIT; it++) {
        asm volatile("cp.async.wait_group 1;" ::: "memory");
        __syncthreads();
        // refill: buffer (it+2)%3 == (it-1)%3, whose compute finished before this sync
        if (it + 2 < NIT) issue(it + 2);
        else asm volatile("cp.async.commit_group;" ::: "memory");

        const unsigned* As = smem_u + (it % 3) * (STAGE_BYTES / 4);
        const unsigned* Bs = As + AS_WORDS;

        #pragma unroll
        for (int ks = 0; ks < 4; ks++) {
            int kq = ks * 8 + c;
            unsigned af[2][4], bf[8][2];
            int m0 = wm * 32 + r;
            #pragma unroll
            for (int fm = 0; fm < 2; fm++) {
                int mr = m0 + fm * 16;
                af[fm][0] = As[mr * 36 + kq];
                af[fm][1] = As[(mr + 8) * 36 + kq];
                af[fm][2] = As[mr * 36 + kq + 4];
                af[fm][3] = As[(mr + 8) * 36 + kq + 4];
            }
            int ncol = wn * 64 + r;
            #pragma unroll
            for (int fn = 0; fn < 8; fn++) {
                bf[fn][0] = Bs[kq * 136 + ncol + fn * 8];
                bf[fn][1] = Bs[(kq + 4) * 136 + ncol + fn * 8];
            }
            #pragma unroll
            for (int fm = 0; fm < 2; fm++)
                #pragma unroll
                for (int fn = 0; fn < 8; fn++)
                    mma_tf32(acc[fm][fn], af[fm], bf[fn][0], bf[fn][1]);
        }
    }

    // epilogue
    #pragma unroll
    for (int fm = 0; fm < 2; fm++) {
        int r_lo = bm + wm * 32 + fm * 16 + r;
        #pragma unroll
        for (int fn = 0; fn < 8; fn++) {
            int col = bn + wn * 64 + fn * 8 + 2 * c;
            float v0 = acc[fm][fn][0], v1 = acc[fm][fn][1];
            float v2 = acc[fm][fn][2], v3 = acc[fm][fn][3];
            if (BIAS) {
                float b0v = bias[col], b1v = bias[col + 1];
                v0 += b0v; v1 += b1v; v2 += b0v; v3 += b1v;
            }
            if (GELU_) { v0 = gelu_f(v0); v1 = gelu_f(v1); v2 = gelu_f(v2); v3 = gelu_f(v3); }
            if (ROUND) { v0 = round_tf32(v0); v1 = round_tf32(v1); v2 = round_tf32(v2); v3 = round_tf32(v3); }
            if (RES) {
                float2 r0 = *(const float2*)(res + (size_t)r_lo * N + col);
                float2 r1 = *(const float2*)(res + (size_t)(r_lo + 8) * N + col);
                v0 += r0.x; v1 += r0.y; v2 += r1.x; v3 += r1.y;
            }
            *(float2*)(C + (size_t)r_lo * N + col)       = make_float2(v0, v1);
            *(float2*)(C + (size_t)(r_lo + 8) * N + col) = make_float2(v2, v3);
        }
    }
}

// ---------------- banded attention, tensor-core (tf32 mma + register flash softmax) ----
#define QP_PAD 68
#define V_PAD  72
#define ATTN_SMEM_WORDS (2 * 64 * QP_PAD + 64 * V_PAD + 258)

__global__ __launch_bounds__(128) void attn_mma(const float* __restrict__ Q,
                                                const float* __restrict__ Kb,
                                                const float* __restrict__ Vb,
                                                const float* __restrict__ rel_emb,
                                                float* __restrict__ O) {
    extern __shared__ unsigned smem_u[];
    unsigned (*Qs)[QP_PAD] = (unsigned(*)[QP_PAD])smem_u;            // also Ps
    unsigned (*Ks)[QP_PAD] = (unsigned(*)[QP_PAD])(smem_u + 64 * QP_PAD);
    unsigned (*Vs)[V_PAD]  = (unsigned(*)[V_PAD]) (smem_u + 2 * 64 * QP_PAD);
    float* bias_s = (float*)(smem_u + 2 * 64 * QP_PAD + 64 * V_PAD);

    int n = blockIdx.x, h = blockIdx.y;
    int tid = threadIdx.x, lane = tid & 31, wid = tid >> 5;
    int r = lane >> 2, c = lane & 3;

    for (int t = tid; t < 1024; t += 128) {
        int i = t >> 4, d4 = (t & 15) * 4;
        float4 q = *(const float4*)(Q + (size_t)(n * 64 + i) * DM_ + h * 64 + d4);
        Qs[i][d4 + 0] = f2tf32(q.x * 0.125f);
        Qs[i][d4 + 1] = f2tf32(q.y * 0.125f);
        Qs[i][d4 + 2] = f2tf32(q.z * 0.125f);
        Qs[i][d4 + 3] = f2tf32(q.w * 0.125f);
    }
    for (int t = tid; t < 258; t += 128) bias_s[t] = rel_emb[t * H_ + h];
    __syncthreads();

    unsigned qf[8][4];
    int row0 = wid * 16 + r;
    #pragma unroll
    for (int kk = 0; kk < 8; kk++) {
        qf[kk][0] = Qs[row0][kk * 8 + c];
        qf[kk][1] = Qs[row0 + 8][kk * 8 + c];
        qf[kk][2] = Qs[row0][kk * 8 + c + 4];
        qf[kk][3] = Qs[row0 + 8][kk * 8 + c + 4];
    }

    float of[8][4];
    #pragma unroll
    for (int f = 0; f < 8; f++)
        #pragma unroll
        for (int e = 0; e < 4; e++) of[f][e] = 0.f;
    float m0 = -1e30f, m1 = -1e30f, l0 = 0.f, l1 = 0.f;

    int w0 = (n >= W_ - 1) ? 0 : (W_ - 1 - n);
    for (int w = w0; w < W_; w++) {
        int sb = n - (W_ - 1) + w;
        __syncthreads();
        for (int t = tid; t < 1024; t += 128) {
            int j = t >> 4, d4 = (t & 15) * 4;
            const float* kp = Kb + (size_t)(sb * 64 + j) * DM_ + h * 64 + d4;
            const float* vp = Vb + (size_t)(sb * 64 + j) * DM_ + h * 64 + d4;
            float4 kx = *(const float4*)kp;
            float4 vx = *(const float4*)vp;
            Ks[j][d4 + 0] = f2tf32(kx.x); Ks[j][d4 + 1] = f2tf32(kx.y);
            Ks[j][d4 + 2] = f2tf32(kx.z); Ks[j][d4 + 3] = f2tf32(kx.w);
            Vs[j][d4 + 0] = f2tf32(vx.x); Vs[j][d4 + 1] = f2tf32(vx.y);
            Vs[j][d4 + 2] = f2tf32(vx.z); Vs[j][d4 + 3] = f2tf32(vx.w);
        }
        __syncthreads();

        float sf[8][4];
        #pragma unroll
        for (int f = 0; f < 8; f++)
            #pragma unroll
            for (int e = 0; e < 4; e++) sf[f][e] = 0.f;
        #pragma unroll
        for (int kk = 0; kk < 8; kk++) {
            #pragma unroll
            for (int f = 0; f < 8; f++) {
                unsigned b0 = Ks[f * 8 + r][kk * 8 + c];
                unsigned b1 = Ks[f * 8 + r][kk * 8 + c + 4];
                mma_tf32(sf[f], qf[kk], b0, b1);
            }
        }

        int base = (W_ - 1 - w) * 64;
        bool last = (w == W_ - 1);
        float mx0 = -1e30f, mx1 = -1e30f;
        #pragma unroll
        for (int f = 0; f < 8; f++) {
            #pragma unroll
            for (int e = 0; e < 2; e++) {
                int j = f * 8 + 2 * c + e;
                int d0 = base + row0 - j;
                int d1 = d0 + 8;
                float v0 = sf[f][e]     + bias_s[max(min(d0, 256) + 1, 0)];
                float v1 = sf[f][e + 2] + bias_s[max(min(d1, 256) + 1, 0)];
                if (last && d0 < 0) v0 = -1e30f;
                if (last && d1 < 0) v1 = -1e30f;
                sf[f][e] = v0; sf[f][e + 2] = v1;
                mx0 = fmaxf(mx0, v0); mx1 = fmaxf(mx1, v1);
            }
        }
        mx0 = fmaxf(mx0, __shfl_xor_sync(0xffffffffu, mx0, 1));
        mx0 = fmaxf(mx0, __shfl_xor_sync(0xffffffffu, mx0, 2));
        mx1 = fmaxf(mx1, __shfl_xor_sync(0xffffffffu, mx1, 1));
        mx1 = fmaxf(mx1, __shfl_xor_sync(0xffffffffu, mx1, 2));
        float mn0 = fmaxf(m0, mx0), mn1 = fmaxf(m1, mx1);
        float sc0 = __expf(m0 - mn0), sc1 = __expf(m1 - mn1);
        m0 = mn0; m1 = mn1;

        float s0 = 0.f, s1 = 0.f;
        #pragma unroll
        for (int f = 0; f < 8; f++) {
            #pragma unroll
            for (int e = 0; e < 2; e++) {
                int col = f * 8 + 2 * c + e;
                float p0 = __expf(sf[f][e]     - mn0);
                float p1 = __expf(sf[f][e + 2] - mn1);
                s0 += p0; s1 += p1;
                Qs[row0][col]     = f2tf32(p0);
                Qs[row0 + 8][col] = f2tf32(p1);
            }
        }
        s0 += __shfl_xor_sync(0xffffffffu, s0, 1);
        s0 += __shfl_xor_sync(0xffffffffu, s0, 2);
        s1 += __shfl_xor_sync(0xffffffffu, s1, 1);
        s1 += __shfl_xor_sync(0xffffffffu, s1, 2);
        l0 = l0 * sc0 + s0;
        l1 = l1 * sc1 + s1;
        #pragma unroll
        for (int f = 0; f < 8; f++) {
            of[f][0] *= sc0; of[f][1] *= sc0;
            of[f][2] *= sc1; of[f][3] *= sc1;
        }
        __syncwarp();

        #pragma unroll
        for (int kk = 0; kk < 8; kk++) {
            unsigned pa[4];
            pa[0] = Qs[row0][kk * 8 + c];
            pa[1] = Qs[row0 + 8][kk * 8 + c];
            pa[2] = Qs[row0][kk * 8 + c + 4];
            pa[3] = Qs[row0 + 8][kk * 8 + c + 4];
            #pragma unroll
            for (int f = 0; f < 8; f++) {
                unsigned b0 = Vs[kk * 8 + c][f * 8 + r];
                unsigned b1 = Vs[kk * 8 + c + 4][f * 8 + r];
                mma_tf32(of[f], pa, b0, b1);
            }
        }
    }

    float invl0 = 1.f / l0, invl1 = 1.f / l1;
    #pragma unroll
    for (int f = 0; f < 8; f++) {
        int col = f * 8 + 2 * c;
        *(float2*)(O + (size_t)(n * 64 + row0) * DM_ + h * 64 + col) =
            make_float2(round_tf32(of[f][0] * invl0), round_tf32(of[f][1] * invl0));
        *(float2*)(O + (size_t)(n * 64 + row0 + 8) * DM_ + h * 64 + col) =
            make_float2(round_tf32(of[f][2] * invl1), round_tf32(of[f][3] * invl1));
    }
}

// ---------------- launch ----------------
extern "C" void kernel_launch(void* const* d_in, const int* in_sizes, int n_in,
                              void* d_out, int out_size) {
    (void)in_sizes; (void)n_in; (void)out_size;
    const float* x      = (const float*)d_in[0];
    const float* Wq     = (const float*)d_in[1];
    const float* Wk     = (const float*)d_in[2];
    const float* Wv     = (const float*)d_in[3];
    const float* Wo     = (const float*)d_in[4];
    const float* rel    = (const float*)d_in[5];
    const float* ln1g   = (const float*)d_in[6];
    const float* ln1b   = (const float*)d_in[7];
    const float* ln2g   = (const float*)d_in[8];
    const float* ln2b   = (const float*)d_in[9];
    const float* W1     = (const float*)d_in[10];
    const float* b1     = (const float*)d_in[11];
    const float* W2     = (const float*)d_in[12];
    const float* b2     = (const float*)d_in[13];
    float* out = (float*)d_out;

    float *Hb, *Qb, *Kb, *Vb, *Ob, *X1, *Gb;
    float *WqR, *WkR, *WvR, *WoR, *W1R, *W2R;
    cudaGetSymbolAddress((void**)&Hb, g_H);
    cudaGetSymbolAddress((void**)&Qb, g_Q);
    cudaGetSymbolAddress((void**)&Kb, g_K);
    cudaGetSymbolAddress((void**)&Vb, g_V);
    cudaGetSymbolAddress((void**)&Ob, g_O);
    cudaGetSymbolAddress((void**)&X1, g_X1);
    cudaGetSymbolAddress((void**)&Gb, g_G);
    cudaGetSymbolAddress((void**)&WqR, g_WqR);
    cudaGetSymbolAddress((void**)&WkR, g_WkR);
    cudaGetSymbolAddress((void**)&WvR, g_WvR);
    cudaGetSymbolAddress((void**)&WoR, g_WoR);
    cudaGetSymbolAddress((void**)&W1R, g_W1R);
    cudaGetSymbolAddress((void**)&W2R, g_W2R);

    const int attn_smem = ATTN_SMEM_WORDS * 4;
    cudaFuncSetAttribute(attn_mma, cudaFuncAttributeMaxDynamicSharedMemorySize, attn_smem);
    cudaFuncSetAttribute(mma_gemm_pipe<false, false, false, false>, cudaFuncAttributeMaxDynamicSharedMemorySize, PIPE_SMEM);
    cudaFuncSetAttribute(mma_gemm_pipe<false, true, false, false>,  cudaFuncAttributeMaxDynamicSharedMemorySize, PIPE_SMEM);
    cudaFuncSetAttribute(mma_gemm_pipe<true, false, true, true>,    cudaFuncAttributeMaxDynamicSharedMemorySize, PIPE_SMEM);
    cudaFuncSetAttribute(mma_gemm_pipe<true, true, false, false>,   cudaFuncAttributeMaxDynamicSharedMemorySize, PIPE_SMEM);

    // 0. round weights to tf32 (RNA)
    round_w<<<DM_ * DM_ / 1024, 256>>>(Wq, WqR, DM_ * DM_);
    round_w<<<DM_ * DM_ / 1024, 256>>>(Wk, WkR, DM_ * DM_);
    round_w<<<DM_ * DM_ / 1024, 256>>>(Wv, WvR, DM_ * DM_);
    round_w<<<DM_ * DM_ / 1024, 256>>>(Wo, WoR, DM_ * DM_);
    round_w<<<DM_ * DFF_ / 1024, 256>>>(W1, W1R, DM_ * DFF_);
    round_w<<<DM_ * DFF_ / 1024, 256>>>(W2, W2R, DM_ * DFF_);

    // 1. h = LN1(x)  (tf32-rounded)
    ln_kernel<<<L_, 256>>>(x, ln1g, ln1b, Hb);

    // 2. fused Q,K,V GEMMs  (grid.z selects weight)
    mma_gemm_pipe<false, false, false, false><<<dim3(DM_ / 128, L_ / 128, 3), 256, PIPE_SMEM>>>(
        Hb, WqR, WkR, WvR, Qb, Kb, Vb, nullptr, nullptr, L_, DM_, DM_);

    // 3. banded attention (writes tf32-rounded Ob)
    attn_mma<<<dim3(NB_, H_), 128, attn_smem>>>(Qb, Kb, Vb, rel, Ob);

    // 4. x1 = x + O @ Wo
    mma_gemm_pipe<false, true, false, false><<<dim3(DM_ / 128, L_ / 128, 1), 256, PIPE_SMEM>>>(
        Ob, WoR, WoR, WoR, X1, X1, X1, nullptr, x, L_, DM_, DM_);

    // 5. h2 = LN2(x1)  (tf32-rounded)
    ln_kernel<<<L_, 256>>>(X1, ln2g, ln2b, Hb);

    // 6. G = gelu(h2 @ W1 + b1)  (tf32-rounded)
    mma_gemm_pipe<true, false, true, true><<<dim3(DFF_ / 128, L_ / 128, 1), 256, PIPE_SMEM>>>(
        Hb, W1R, W1R, W1R, Gb, Gb, Gb, b1, nullptr, L_, DFF_, DM_);

    // 7. out = x1 + G @ W2 + b2
    mma_gemm_pipe<true, true, false, false><<<dim3(DM_ / 128, L_ / 128, 1), 256, PIPE_SMEM>>>(
        Gb, W2R, W2R, W2R, out, out, out, b2, X1, L_, DM_, DFF_);
}

// round 7
// speedup vs baseline: 6.2494x; 1.4757x over previous
#include <cuda_runtime.h>
#include <cuda_fp16.h>
#include <stdint.h>
#include <math.h>

#define L_   4096
#define DM_  1024
#define H_   16
#define DH_  64
#define BS_  64
#define W_   16
#define NB_  64
#define DFF_ 4096

// ---------------- scratch (static __device__ arrays; no allocations) ----------------
__device__ __half g_H [L_ * DM_];   // LN output (half)
__device__ __half g_Q [L_ * DM_];
__device__ __half g_K [L_ * DM_];
__device__ __half g_V [L_ * DM_];
__device__ __half g_O [L_ * DM_];   // attention output (half)
__device__ float  g_X1[L_ * DM_];   // x + attn@Wo (fp32)
__device__ __half g_G [L_ * DFF_];  // gelu(h2@W1+b1) (half)
// packed half weights: P[k2][n] = half2(W[2k2][n], W[2k2+1][n])
__device__ uint32_t g_WqP[DM_ / 2 * DM_];
__device__ uint32_t g_WkP[DM_ / 2 * DM_];
__device__ uint32_t g_WvP[DM_ / 2 * DM_];
__device__ uint32_t g_WoP[DM_ / 2 * DM_];
__device__ uint32_t g_W1P[DM_ / 2 * DFF_];
__device__ uint32_t g_W2P[DFF_ / 2 * DM_];

// ---------------- small helpers ----------------
__device__ __forceinline__ float block_sum(float val, float* red) {
    int t = threadIdx.x;
    #pragma unroll
    for (int o = 16; o > 0; o >>= 1) val += __shfl_xor_sync(0xffffffffu, val, o);
    __syncthreads();
    if ((t & 31) == 0) red[t >> 5] = val;
    __syncthreads();
    if (t == 0) {
        float z = 0.f;
        #pragma unroll
        for (int i = 0; i < 8; i++) z += red[i];
        red[0] = z;
    }
    __syncthreads();
    return red[0];
}

__device__ __forceinline__ float gelu_f(float x) {
    float x3 = x * x * x;
    return 0.5f * x * (1.f + tanhf(0.7978845608028654f * (x + 0.044715f * x3)));
}

__device__ __forceinline__ unsigned f2tf32(float f) {
    unsigned r;
    asm("cvt.rna.tf32.f32 %0, %1;" : "=r"(r) : "f"(f));
    return r;
}

// tf32 mma (attention)
__device__ __forceinline__ void mma_tf32(float* d, const unsigned* a, unsigned b0, unsigned b1) {
    asm volatile(
        "mma.sync.aligned.m16n8k8.row.col.f32.tf32.tf32.f32 "
        "{%0,%1,%2,%3}, {%4,%5,%6,%7}, {%8,%9}, {%0,%1,%2,%3};\n"
        : "+f"(d[0]), "+f"(d[1]), "+f"(d[2]), "+f"(d[3])
        : "r"(a[0]), "r"(a[1]), "r"(a[2]), "r"(a[3]), "r"(b0), "r"(b1));
}

// fp16 mma (GEMMs)
__device__ __forceinline__ void mma_f16(float* d, const unsigned* a, unsigned b0, unsigned b1) {
    asm volatile(
        "mma.sync.aligned.m16n8k16.row.col.f32.f16.f16.f32 "
        "{%0,%1,%2,%3}, {%4,%5,%6,%7}, {%8,%9}, {%0,%1,%2,%3};\n"
        : "+f"(d[0]), "+f"(d[1]), "+f"(d[2]), "+f"(d[3])
        : "r"(a[0]), "r"(a[1]), "r"(a[2]), "r"(a[3]), "r"(b0), "r"(b1));
}

__device__ __forceinline__ uint32_t s2u(const void* p) {
    return (uint32_t)__cvta_generic_to_shared(p);
}

__device__ __forceinline__ void cp16(uint32_t dst, const void* src) {
    asm volatile("cp.async.cg.shared.global [%0], [%1], 16;" :: "r"(dst), "l"(src));
}

__device__ __forceinline__ uint32_t pack_h2(float lo, float hi) {
    __half2 h = __floats2half2_rn(lo, hi);
    return *reinterpret_cast<uint32_t*>(&h);
}

// ---------------- LayerNorm (fp32 in, half out) ----------------
__global__ __launch_bounds__(256) void ln_kernel(const float* __restrict__ x,
                                                 const float* __restrict__ g,
                                                 const float* __restrict__ b,
                                                 __half* __restrict__ out) {
    __shared__ float red[8];
    int row = blockIdx.x;
    const float* xr = x + (size_t)row * DM_;
    int t = threadIdx.x;
    float v[4];
    float s = 0.f;
    #pragma unroll
    for (int i = 0; i < 4; i++) { v[i] = xr[t + i * 256]; s += v[i]; }
    float mean = block_sum(s, red) * (1.f / DM_);
    float s2 = 0.f;
    #pragma unroll
    for (int i = 0; i < 4; i++) { float d = v[i] - mean; s2 += d * d; }
    float var = block_sum(s2, red) * (1.f / DM_);
    float inv = rsqrtf(var + 1e-5f);
    __half* orow = out + (size_t)row * DM_;
    #pragma unroll
    for (int i = 0; i < 4; i++) {
        int c = t + i * 256;
        orow[c] = __float2half((v[i] - mean) * inv * g[c] + b[c]);
    }
}

// ---------------- weight pack: W[K][N] fp32 -> P[K/2][N] uint32(half2) ----------------
__global__ __launch_bounds__(256) void pack_w(const float* __restrict__ Wm,
                                              uint32_t* __restrict__ P,
                                              int K, int N) {
    int npack = N >> 2;
    int idx = blockIdx.x * 256 + threadIdx.x;
    if (idx >= (K >> 1) * npack) return;
    int k2 = idx / npack;
    int n4 = (idx - k2 * npack) * 4;
    float4 r0 = *(const float4*)(Wm + (size_t)(2 * k2) * N + n4);
    float4 r1 = *(const float4*)(Wm + (size_t)(2 * k2 + 1) * N + n4);
    uint32_t* dst = P + (size_t)k2 * N + n4;
    dst[0] = pack_h2(r0.x, r1.x);
    dst[1] = pack_h2(r0.y, r1.y);
    dst[2] = pack_h2(r0.z, r1.z);
    dst[3] = pack_h2(r0.w, r1.w);
}

// ---------------- cp.async pipelined fp16 mma GEMM ----------------
// C = act(A @ B + bias) + res.  A[M][K] half row-major, B packed uint32 [K/2][N].
// BM=BN=128, BK=32; 256 threads = 8 warps (4x2 of 32x64 warp tiles).
// 3 smem stages, 2 cp.async groups in flight. blockIdx.z selects (B, C) pair.
#define AS_WORDS 2560               /* 128 rows * 20 (16 pairs + pad 4) */
#define BSW_WORDS 2176              /* 16 pair-rows * 136 */
#define STAGE_WORDS (AS_WORDS + BSW_WORDS)
#define STAGE_BYTES (STAGE_WORDS * 4)
#define PIPE_SMEM (3 * STAGE_BYTES)

template<bool BIAS, bool RES, bool GELU_, bool HOUT>
__global__ __launch_bounds__(256, 2) void hgemm_pipe(
        const __half* __restrict__ A,
        const uint32_t* __restrict__ B0, const uint32_t* __restrict__ B1, const uint32_t* __restrict__ B2,
        void* __restrict__ C0, void* __restrict__ C1, void* __restrict__ C2,
        const float* __restrict__ bias,
        const float* __restrict__ res,
        int M, int N, int K) {
    extern __shared__ unsigned smem_u[];
    uint32_t sb = s2u(smem_u);

    int tid  = threadIdx.x;
    int lane = tid & 31;
    int wid  = tid >> 5;
    int bm = blockIdx.y * 128, bn = blockIdx.x * 128;
    int wm = wid >> 1, wn = wid & 1;
    int r = lane >> 2, c = lane & 3;

    const uint32_t* B = (blockIdx.z == 0) ? B0 : (blockIdx.z == 1) ? B1 : B2;
    void*           C = (blockIdx.z == 0) ? C0 : (blockIdx.z == 1) ? C1 : C2;

    float acc[2][8][4];
    #pragma unroll
    for (int fm = 0; fm < 2; fm++)
        #pragma unroll
        for (int fn = 0; fn < 8; fn++)
            #pragma unroll
            for (int i = 0; i < 4; i++) acc[fm][fn][i] = 0.f;

    int NIT = K >> 5;
    int K2 = K >> 1;

    auto issue = [&](int it) {
        uint32_t base = sb + (uint32_t)(it % 3) * STAGE_BYTES;
        int k0 = it << 5;      // in halves
        int k2_0 = it << 4;    // in pairs
        #pragma unroll
        for (int p = 0; p < 2; p++) {
            int idx = p * 256 + tid;
            int row = idx >> 2, aq = (idx & 3);          // aq*8 halves = aq*4 words
            cp16(base + (uint32_t)(row * 20 + aq * 4) * 4,
                 A + (size_t)(bm + row) * K + k0 + aq * 8);
        }
        #pragma unroll
        for (int p = 0; p < 2; p++) {
            int idx = p * 256 + tid;
            int row = idx >> 5, n4 = (idx & 31) * 4;
            cp16(base + (uint32_t)(AS_WORDS + row * 136 + n4) * 4,
                 B + (size_t)(k2_0 + row) * N + bn + n4);
        }
        asm volatile("cp.async.commit_group;" ::: "memory");
    };

    issue(0);
    issue(1);

    for (int it = 0; it < NIT; it++) {
        asm volatile("cp.async.wait_group 1;" ::: "memory");
        __syncthreads();
        if (it + 2 < NIT) issue(it + 2);
        else asm volatile("cp.async.commit_group;" ::: "memory");

        const unsigned* As = smem_u + (it % 3) * STAGE_WORDS;
        const unsigned* Bs = As + AS_WORDS;

        #pragma unroll
        for (int kt = 0; kt < 2; kt++) {
            unsigned af[2][4], bf[8][2];
            int m0 = wm * 32 + r;
            #pragma unroll
            for (int fm = 0; fm < 2; fm++) {
                int mr = m0 + fm * 16;
                af[fm][0] = As[mr * 20 + kt * 8 + c];
                af[fm][1] = As[(mr + 8) * 20 + kt * 8 + c];
                af[fm][2] = As[mr * 20 + kt * 8 + c + 4];
                af[fm][3] = As[(mr + 8) * 20 + kt * 8 + c + 4];
            }
            int ncol = wn * 64 + r;
            #pragma unroll
            for (int fn = 0; fn < 8; fn++) {
                bf[fn][0] = Bs[(kt * 8 + c) * 136 + ncol + fn * 8];
                bf[fn][1] = Bs[(kt * 8 + c + 4) * 136 + ncol + fn * 8];
            }
            #pragma unroll
            for (int fm = 0; fm < 2; fm++)
                #pragma unroll
                for (int fn = 0; fn < 8; fn++)
                    mma_f16(acc[fm][fn], af[fm], bf[fn][0], bf[fn][1]);
        }
    }
    (void)K2;

    // epilogue
    #pragma unroll
    for (int fm = 0; fm < 2; fm++) {
        int r_lo = bm + wm * 32 + fm * 16 + r;
        #pragma unroll
        for (int fn = 0; fn < 8; fn++) {
            int col = bn + wn * 64 + fn * 8 + 2 * c;
            float v0 = acc[fm][fn][0], v1 = acc[fm][fn][1];
            float v2 = acc[fm][fn][2], v3 = acc[fm][fn][3];
            if (BIAS) {
                float b0v = bias[col], b1v = bias[col + 1];
                v0 += b0v; v1 += b1v; v2 += b0v; v3 += b1v;
            }
            if (GELU_) { v0 = gelu_f(v0); v1 = gelu_f(v1); v2 = gelu_f(v2); v3 = gelu_f(v3); }
            if (RES) {
                float2 r0 = *(const float2*)(res + (size_t)r_lo * N + col);
                float2 r1 = *(const float2*)(res + (size_t)(r_lo + 8) * N + col);
                v0 += r0.x; v1 += r0.y; v2 += r1.x; v3 += r1.y;
            }
            if (HOUT) {
                __half* Ch = (__half*)C;
                *(uint32_t*)(Ch + (size_t)r_lo * N + col)       = pack_h2(v0, v1);
                *(uint32_t*)(Ch + (size_t)(r_lo + 8) * N + col) = pack_h2(v2, v3);
            } else {
                float* Cf = (float*)C;
                *(float2*)(Cf + (size_t)r_lo * N + col)       = make_float2(v0, v1);
                *(float2*)(Cf + (size_t)(r_lo + 8) * N + col) = make_float2(v2, v3);
            }
        }
    }
}

// ---------------- banded attention (tf32 mma, half I/O) ----------------
#define QP_PAD 68
#define V_PAD  72
#define ATTN_SMEM_WORDS (2 * 64 * QP_PAD + 64 * V_PAD + 258)

__global__ __launch_bounds__(128) void attn_mma(const __half* __restrict__ Q,
                                                const __half* __restrict__ Kb,
                                                const __half* __restrict__ Vb,
                                                const float* __restrict__ rel_emb,
                                                __half* __restrict__ O) {
    extern __shared__ unsigned smem_u[];
    unsigned (*Qs)[QP_PAD] = (unsigned(*)[QP_PAD])smem_u;            // also Ps
    unsigned (*Ks)[QP_PAD] = (unsigned(*)[QP_PAD])(smem_u + 64 * QP_PAD);
    unsigned (*Vs)[V_PAD]  = (unsigned(*)[V_PAD]) (smem_u + 2 * 64 * QP_PAD);
    float* bias_s = (float*)(smem_u + 2 * 64 * QP_PAD + 64 * V_PAD);

    int n = blockIdx.x, h = blockIdx.y;
    int tid = threadIdx.x, lane = tid & 31, wid = tid >> 5;
    int r = lane >> 2, c = lane & 3;

    // load Q (half -> scaled tf32)
    for (int t = tid; t < 512; t += 128) {
        int i = t >> 3, d8 = (t & 7) * 8;
        uint4 v = *(const uint4*)(Q + (size_t)(n * 64 + i) * DM_ + h * 64 + d8);
        const __half2* hp = (const __half2*)&v;
        #pragma unroll
        for (int q = 0; q < 4; q++) {
            float2 f = __half22float2(hp[q]);
            Qs[i][d8 + 2 * q]     = f2tf32(f.x * 0.125f);
            Qs[i][d8 + 2 * q + 1] = f2tf32(f.y * 0.125f);
        }
    }
    for (int t = tid; t < 258; t += 128) bias_s[t] = rel_emb[t * H_ + h];
    __syncthreads();

    unsigned qf[8][4];
    int row0 = wid * 16 + r;
    #pragma unroll
    for (int kk = 0; kk < 8; kk++) {
        qf[kk][0] = Qs[row0][kk * 8 + c];
        qf[kk][1] = Qs[row0 + 8][kk * 8 + c];
        qf[kk][2] = Qs[row0][kk * 8 + c + 4];
        qf[kk][3] = Qs[row0 + 8][kk * 8 + c + 4];
    }

    float of[8][4];
    #pragma unroll
    for (int f = 0; f < 8; f++)
        #pragma unroll
        for (int e = 0; e < 4; e++) of[f][e] = 0.f;
    float m0 = -1e30f, m1 = -1e30f, l0 = 0.f, l1 = 0.f;

    int w0 = (n >= W_ - 1) ? 0 : (W_ - 1 - n);
    for (int w = w0; w < W_; w++) {
        int sb = n - (W_ - 1) + w;
        __syncthreads();
        for (int t = tid; t < 512; t += 128) {
            int j = t >> 3, d8 = (t & 7) * 8;
            uint4 kv = *(const uint4*)(Kb + (size_t)(sb * 64 + j) * DM_ + h * 64 + d8);
            uint4 vv = *(const uint4*)(Vb + (size_t)(sb * 64 + j) * DM_ + h * 64 + d8);
            const __half2* kp = (const __half2*)&kv;
            const __half2* vp = (const __half2*)&vv;
            #pragma unroll
            for (int q = 0; q < 4; q++) {
                float2 fk = __half22float2(kp[q]);
                float2 fv = __half22float2(vp[q]);
                Ks[j][d8 + 2 * q]     = f2tf32(fk.x);
                Ks[j][d8 + 2 * q + 1] = f2tf32(fk.y);
                Vs[j][d8 + 2 * q]     = f2tf32(fv.x);
                Vs[j][d8 + 2 * q + 1] = f2tf32(fv.y);
            }
        }
        __syncthreads();

        float sf[8][4];
        #pragma unroll
        for (int f = 0; f < 8; f++)
            #pragma unroll
            for (int e = 0; e < 4; e++) sf[f][e] = 0.f;
        #pragma unroll
        for (int kk = 0; kk < 8; kk++) {
            #pragma unroll
            for (int f = 0; f < 8; f++) {
                unsigned b0 = Ks[f * 8 + r][kk * 8 + c];
                unsigned b1 = Ks[f * 8 + r][kk * 8 + c + 4];
                mma_tf32(sf[f], qf[kk], b0, b1);
            }
        }

        int base = (W_ - 1 - w) * 64;
        bool last = (w == W_ - 1);
        float mx0 = -1e30f, mx1 = -1e30f;
        #pragma unroll
        for (int f = 0; f < 8; f++) {
            #pragma unroll
            for (int e = 0; e < 2; e++) {
                int j = f * 8 + 2 * c + e;
                int d0 = base + row0 - j;
                int d1 = d0 + 8;
                float v0 = sf[f][e]     + bias_s[max(min(d0, 256) + 1, 0)];
                float v1 = sf[f][e + 2] + bias_s[max(min(d1, 256) + 1, 0)];
                if (last && d0 < 0) v0 = -1e30f;
                if (last && d1 < 0) v1 = -1e30f;
                sf[f][e] = v0; sf[f][e + 2] = v1;
                mx0 = fmaxf(mx0, v0); mx1 = fmaxf(mx1, v1);
            }
        }
        mx0 = fmaxf(mx0, __shfl_xor_sync(0xffffffffu, mx0, 1));
        mx0 = fmaxf(mx0, __shfl_xor_sync(0xffffffffu, mx0, 2));
        mx1 = fmaxf(mx1, __shfl_xor_sync(0xffffffffu, mx1, 1));
        mx1 = fmaxf(mx1, __shfl_xor_sync(0xffffffffu, mx1, 2));
        float mn0 = fmaxf(m0, mx0), mn1 = fmaxf(m1, mx1);
        float sc0 = __expf(m0 - mn0), sc1 = __expf(m1 - mn1);
        m0 = mn0; m1 = mn1;

        float s0 = 0.f, s1 = 0.f;
        #pragma unroll
        for (int f = 0; f < 8; f++) {
            #pragma unroll
            for (int e = 0; e < 2; e++) {
                int col = f * 8 + 2 * c + e;
                float p0 = __expf(sf[f][e]     - mn0);
                float p1 = __expf(sf[f][e + 2] - mn1);
                s0 += p0; s1 += p1;
                Qs[row0][col]     = f2tf32(p0);
                Qs[row0 + 8][col] = f2tf32(p1);
            }
        }
        s0 += __shfl_xor_sync(0xffffffffu, s0, 1);
        s0 += __shfl_xor_sync(0xffffffffu, s0, 2);
        s1 += __shfl_xor_sync(0xffffffffu, s1, 1);
        s1 += __shfl_xor_sync(0xffffffffu, s1, 2);
        l0 = l0 * sc0 + s0;
        l1 = l1 * sc1 + s1;
        #pragma unroll
        for (int f = 0; f < 8; f++) {
            of[f][0] *= sc0; of[f][1] *= sc0;
            of[f][2] *= sc1; of[f][3] *= sc1;
        }
        __syncwarp();

        #pragma unroll
        for (int kk = 0; kk < 8; kk++) {
            unsigned pa[4];
            pa[0] = Qs[row0][kk * 8 + c];
            pa[1] = Qs[row0 + 8][kk * 8 + c];
            pa[2] = Qs[row0][kk * 8 + c + 4];
            pa[3] = Qs[row0 + 8][kk * 8 + c + 4];
            #pragma unroll
            for (int f = 0; f < 8; f++) {
                unsigned b0 = Vs[kk * 8 + c][f * 8 + r];
                unsigned b1 = Vs[kk * 8 + c + 4][f * 8 + r];
                mma_tf32(of[f], pa, b0, b1);
            }
        }
    }

    float invl0 = 1.f / l0, invl1 = 1.f / l1;
    #pragma unroll
    for (int f = 0; f < 8; f++) {
        int col = f * 8 + 2 * c;
        *(uint32_t*)(O + (size_t)(n * 64 + row0) * DM_ + h * 64 + col) =
            pack_h2(of[f][0] * invl0, of[f][1] * invl0);
        *(uint32_t*)(O + (size_t)(n * 64 + row0 + 8) * DM_ + h * 64 + col) =
            pack_h2(of[f][2] * invl1, of[f][3] * invl1);
    }
}

// ---------------- launch ----------------
extern "C" void kernel_launch(void* const* d_in, const int* in_sizes, int n_in,
                              void* d_out, int out_size) {
    (void)in_sizes; (void)n_in; (void)out_size;
    const float* x      = (const float*)d_in[0];
    const float* Wq     = (const float*)d_in[1];
    const float* Wk     = (const float*)d_in[2];
    const float* Wv     = (const float*)d_in[3];
    const float* Wo     = (const float*)d_in[4];
    const float* rel    = (const float*)d_in[5];
    const float* ln1g   = (const float*)d_in[6];
    const float* ln1b   = (const float*)d_in[7];
    const float* ln2g   = (const float*)d_in[8];
    const float* ln2b   = (const float*)d_in[9];
    const float* W1     = (const float*)d_in[10];
    const float* b1     = (const float*)d_in[11];
    const float* W2     = (const float*)d_in[12];
    const float* b2     = (const float*)d_in[13];
    float* out = (float*)d_out;

    __half *Hb, *Qb, *Kb, *Vb, *Ob, *Gb;
    float *X1;
    uint32_t *WqP, *WkP, *WvP, *WoP, *W1P, *W2P;
    cudaGetSymbolAddress((void**)&Hb, g_H);
    cudaGetSymbolAddress((void**)&Qb, g_Q);
    cudaGetSymbolAddress((void**)&Kb, g_K);
    cudaGetSymbolAddress((void**)&Vb, g_V);
    cudaGetSymbolAddress((void**)&Ob, g_O);
    cudaGetSymbolAddress((void**)&X1, g_X1);
    cudaGetSymbolAddress((void**)&Gb, g_G);
    cudaGetSymbolAddress((void**)&WqP, g_WqP);
    cudaGetSymbolAddress((void**)&WkP, g_WkP);
    cudaGetSymbolAddress((void**)&WvP, g_WvP);
    cudaGetSymbolAddress((void**)&WoP, g_WoP);
    cudaGetSymbolAddress((void**)&W1P, g_W1P);
    cudaGetSymbolAddress((void**)&W2P, g_W2P);

    const int attn_smem = ATTN_SMEM_WORDS * 4;
    cudaFuncSetAttribute(attn_mma, cudaFuncAttributeMaxDynamicSharedMemorySize, attn_smem);
    cudaFuncSetAttribute(hgemm_pipe<false, false, false, true>,  cudaFuncAttributeMaxDynamicSharedMemorySize, PIPE_SMEM);
    cudaFuncSetAttribute(hgemm_pipe<false, true, false, false>,  cudaFuncAttributeMaxDynamicSharedMemorySize, PIPE_SMEM);
    cudaFuncSetAttribute(hgemm_pipe<true, false, true, true>,    cudaFuncAttributeMaxDynamicSharedMemorySize, PIPE_SMEM);
    cudaFuncSetAttribute(hgemm_pipe<true, true, false, false>,   cudaFuncAttributeMaxDynamicSharedMemorySize, PIPE_SMEM);

    // 0. pack weights to half2
    pack_w<<<(DM_ / 2) * (DM_ / 4) / 256, 256>>>(Wq, WqP, DM_, DM_);
    pack_w<<<(DM_ / 2) * (DM_ / 4) / 256, 256>>>(Wk, WkP, DM_, DM_);
    pack_w<<<(DM_ / 2) * (DM_ / 4) / 256, 256>>>(Wv, WvP, DM_, DM_);
    pack_w<<<(DM_ / 2) * (DM_ / 4) / 256, 256>>>(Wo, WoP, DM_, DM_);
    pack_w<<<(DM_ / 2) * (DFF_ / 4) / 256, 256>>>(W1, W1P, DM_, DFF_);
    pack_w<<<(DFF_ / 2) * (DM_ / 4) / 256, 256>>>(W2, W2P, DFF_, DM_);

    // 1. h = LN1(x)  (half)
    ln_kernel<<<L_, 256>>>(x, ln1g, ln1b, Hb);

    // 2. fused Q,K,V GEMMs
    hgemm_pipe<false, false, false, true><<<dim3(DM_ / 128, L_ / 128, 3), 256, PIPE_SMEM>>>(
        Hb, WqP, WkP, WvP, Qb, Kb, Vb, nullptr, nullptr, L_, DM_, DM_);

    // 3. banded attention (half I/O)
    attn_mma<<<dim3(NB_, H_), 128, attn_smem>>>(Qb, Kb, Vb, rel, Ob);

    // 4. x1 = x + O @ Wo  (fp32 out)
    hgemm_pipe<false, true, false, false><<<dim3(DM_ / 128, L_ / 128, 1), 256, PIPE_SMEM>>>(
        Ob, WoP, WoP, WoP, X1, X1, X1, nullptr, x, L_, DM_, DM_);

    // 5. h2 = LN2(x1)  (half)
    ln_kernel<<<L_, 256>>>(X1, ln2g, ln2b, Hb);

    // 6. G = gelu(h2 @ W1 + b1)  (half)
    hgemm_pipe<true, false, true, true><<<dim3(DFF_ / 128, L_ / 128, 1), 256, PIPE_SMEM>>>(
        Hb, W1P, W1P, W1P, Gb, Gb, Gb, b1, nullptr, L_, DFF_, DM_);

    // 7. out = x1 + G @ W2 + b2  (fp32 out)
    hgemm_pipe<true, true, false, false><<<dim3(DM_ / 128, L_ / 128, 1), 256, PIPE_SMEM>>>(
        Gb, W2P, W2P, W2P, out, out, out, b2, X1, L_, DM_, DFF_);
}

// round 8
// speedup vs baseline: 6.7047x; 1.0729x over previous
#include <cuda_runtime.h>
#include <cuda_fp16.h>
#include <stdint.h>
#include <math.h>

#define L_   4096
#define DM_  1024
#define H_   16
#define DH_  64
#define BS_  64
#define W_   16
#define NB_  64
#define DFF_ 4096

// ---------------- scratch (static __device__ arrays; no allocations) ----------------
__device__ __half g_H [L_ * DM_];   // LN output (half)
__device__ __half g_Q [L_ * DM_];
__device__ __half g_K [L_ * DM_];
__device__ __half g_V [L_ * DM_];
__device__ __half g_O [L_ * DM_];   // attention output (half)
__device__ float  g_X1[L_ * DM_];   // x + attn@Wo (fp32)
__device__ __half g_G [L_ * DFF_];  // gelu(h2@W1+b1) (half)
// half weights, same [K][N] layout
__device__ __half g_WqH[DM_ * DM_];
__device__ __half g_WkH[DM_ * DM_];
__device__ __half g_WvH[DM_ * DM_];
__device__ __half g_WoH[DM_ * DM_];
__device__ __half g_W1H[DM_ * DFF_];
__device__ __half g_W2H[DFF_ * DM_];

// ---------------- small helpers ----------------
__device__ __forceinline__ float block_sum(float val, float* red) {
    int t = threadIdx.x;
    #pragma unroll
    for (int o = 16; o > 0; o >>= 1) val += __shfl_xor_sync(0xffffffffu, val, o);
    __syncthreads();
    if ((t & 31) == 0) red[t >> 5] = val;
    __syncthreads();
    if (t == 0) {
        float z = 0.f;
        #pragma unroll
        for (int i = 0; i < 8; i++) z += red[i];
        red[0] = z;
    }
    __syncthreads();
    return red[0];
}

__device__ __forceinline__ float gelu_f(float x) {
    float x3 = x * x * x;
    return 0.5f * x * (1.f + tanhf(0.7978845608028654f * (x + 0.044715f * x3)));
}

__device__ __forceinline__ unsigned f2tf32(float f) {
    unsigned r;
    asm("cvt.rna.tf32.f32 %0, %1;" : "=r"(r) : "f"(f));
    return r;
}

__device__ __forceinline__ void mma_tf32(float* d, const unsigned* a, unsigned b0, unsigned b1) {
    asm volatile(
        "mma.sync.aligned.m16n8k8.row.col.f32.tf32.tf32.f32 "
        "{%0,%1,%2,%3}, {%4,%5,%6,%7}, {%8,%9}, {%0,%1,%2,%3};\n"
        : "+f"(d[0]), "+f"(d[1]), "+f"(d[2]), "+f"(d[3])
        : "r"(a[0]), "r"(a[1]), "r"(a[2]), "r"(a[3]), "r"(b0), "r"(b1));
}

__device__ __forceinline__ void mma_f16(float* d, const unsigned* a, unsigned b0, unsigned b1) {
    asm volatile(
        "mma.sync.aligned.m16n8k16.row.col.f32.f16.f16.f32 "
        "{%0,%1,%2,%3}, {%4,%5,%6,%7}, {%8,%9}, {%0,%1,%2,%3};\n"
        : "+f"(d[0]), "+f"(d[1]), "+f"(d[2]), "+f"(d[3])
        : "r"(a[0]), "r"(a[1]), "r"(a[2]), "r"(a[3]), "r"(b0), "r"(b1));
}

__device__ __forceinline__ void ldsm_x4(unsigned& r0, unsigned& r1, unsigned& r2, unsigned& r3,
                                        uint32_t addr) {
    asm volatile("ldmatrix.sync.aligned.m8n8.x4.shared.b16 {%0,%1,%2,%3}, [%4];"
                 : "=r"(r0), "=r"(r1), "=r"(r2), "=r"(r3) : "r"(addr));
}
__device__ __forceinline__ void ldsm_x4_t(unsigned& r0, unsigned& r1, unsigned& r2, unsigned& r3,
                                          uint32_t addr) {
    asm volatile("ldmatrix.sync.aligned.m8n8.x4.trans.shared.b16 {%0,%1,%2,%3}, [%4];"
                 : "=r"(r0), "=r"(r1), "=r"(r2), "=r"(r3) : "r"(addr));
}

__device__ __forceinline__ uint32_t s2u(const void* p) {
    return (uint32_t)__cvta_generic_to_shared(p);
}

__device__ __forceinline__ void cp16(uint32_t dst, const void* src) {
    asm volatile("cp.async.cg.shared.global [%0], [%1], 16;" :: "r"(dst), "l"(src));
}

__device__ __forceinline__ uint32_t pack_h2(float lo, float hi) {
    __half2 h = __floats2half2_rn(lo, hi);
    return *reinterpret_cast<uint32_t*>(&h);
}

// ---------------- LayerNorm (fp32 in, half out) ----------------
__global__ __launch_bounds__(256) void ln_kernel(const float* __restrict__ x,
                                                 const float* __restrict__ g,
                                                 const float* __restrict__ b,
                                                 __half* __restrict__ out) {
    __shared__ float red[8];
    int row = blockIdx.x;
    const float* xr = x + (size_t)row * DM_;
    int t = threadIdx.x;
    float v[4];
    float s = 0.f;
    #pragma unroll
    for (int i = 0; i < 4; i++) { v[i] = xr[t + i * 256]; s += v[i]; }
    float mean = block_sum(s, red) * (1.f / DM_);
    float s2 = 0.f;
    #pragma unroll
    for (int i = 0; i < 4; i++) { float d = v[i] - mean; s2 += d * d; }
    float var = block_sum(s2, red) * (1.f / DM_);
    float inv = rsqrtf(var + 1e-5f);
    __half* orow = out + (size_t)row * DM_;
    #pragma unroll
    for (int i = 0; i < 4; i++) {
        int c = t + i * 256;
        orow[c] = __float2half((v[i] - mean) * inv * g[c] + b[c]);
    }
}

// ---------------- fused weight convert fp32 -> half (all 6 weights, 1 launch) --------
#define SMALL8 (DM_ * DM_ / 8)
__global__ __launch_bounds__(256) void cvt_all(
        const float* __restrict__ s0, const float* __restrict__ s1,
        const float* __restrict__ s2, const float* __restrict__ s3,
        const float* __restrict__ s4, const float* __restrict__ s5,
        __half* __restrict__ d0, __half* __restrict__ d1,
        __half* __restrict__ d2, __half* __restrict__ d3,
        __half* __restrict__ d4, __half* __restrict__ d5) {
    long i = (long)blockIdx.x * 256 + threadIdx.x;   // unit = 8 floats
    const float* src; __half* dst; long off;
    if      (i < 1 * SMALL8)               { src = s0; dst = d0; off = i; }
    else if (i < 2 * SMALL8)               { src = s1; dst = d1; off = i - 1 * SMALL8; }
    else if (i < 3 * SMALL8)               { src = s2; dst = d2; off = i - 2 * SMALL8; }
    else if (i < 4 * SMALL8)               { src = s3; dst = d3; off = i - 3 * SMALL8; }
    else if (i < 4 * SMALL8 + 4 * SMALL8)  { src = s4; dst = d4; off = i - 4 * SMALL8; }
    else                                   { src = s5; dst = d5; off = i - 8 * SMALL8; }
    long e = off * 8;
    float4 a = *(const float4*)(src + e);
    float4 b = *(const float4*)(src + e + 4);
    uint4 o;
    o.x = pack_h2(a.x, a.y); o.y = pack_h2(a.z, a.w);
    o.z = pack_h2(b.x, b.y); o.w = pack_h2(b.z, b.w);
    *(uint4*)(dst + e) = o;
}

// ---------------- ldmatrix fp16 GEMM: C = act(A @ B + bias) + res ----------------
// A[M][K] half row-major, B[K][N] half row-major.
// BM=BN=128, BK=32; 256 threads = 8 warps (4x2 of 32x64 warp tiles).
// smem: A halves [128][40] (80B stride), B halves [32][136] (272B stride). 3 stages.
#define A_STAGE_BYTES (128 * 80)
#define B_STAGE_BYTES (32 * 272)
#define STAGE_BYTES (A_STAGE_BYTES + B_STAGE_BYTES)
#define PIPE_SMEM (3 * STAGE_BYTES)

template<bool BIAS, bool RES, bool GELU_, bool HOUT>
__global__ __launch_bounds__(256, 2) void hgemm_pipe(
        const __half* __restrict__ A,
        const __half* __restrict__ B0, const __half* __restrict__ B1, const __half* __restrict__ B2,
        void* __restrict__ C0, void* __restrict__ C1, void* __restrict__ C2,
        const float* __restrict__ bias,
        const float* __restrict__ res,
        int M, int N, int K) {
    extern __shared__ char smem_c[];
    uint32_t sb = s2u(smem_c);

    int tid  = threadIdx.x;
    int lane = tid & 31;
    int wid  = tid >> 5;
    int bm = blockIdx.y * 128, bn = blockIdx.x * 128;
    int wm = wid >> 1, wn = wid & 1;
    int r = lane >> 2, c = lane & 3;

    const __half* B = (blockIdx.z == 0) ? B0 : (blockIdx.z == 1) ? B1 : B2;
    void*         C = (blockIdx.z == 0) ? C0 : (blockIdx.z == 1) ? C1 : C2;

    float acc[2][8][4];
    #pragma unroll
    for (int fm = 0; fm < 2; fm++)
        #pragma unroll
        for (int fn = 0; fn < 8; fn++)
            #pragma unroll
            for (int i = 0; i < 4; i++) acc[fm][fn][i] = 0.f;

    int NIT = K >> 5;

    auto issue = [&](int it) {
        uint32_t base = sb + (uint32_t)(it % 3) * STAGE_BYTES;
        int k0 = it << 5;
        #pragma unroll
        for (int p = 0; p < 2; p++) {
            int idx = p * 256 + tid;
            int row = idx >> 2, aq = idx & 3;
            cp16(base + (uint32_t)(row * 80 + aq * 16),
                 A + (size_t)(bm + row) * K + k0 + aq * 8);
        }
        #pragma unroll
        for (int p = 0; p < 2; p++) {
            int idx = p * 256 + tid;
            int row = idx >> 4, nq = idx & 15;
            cp16(base + (uint32_t)(A_STAGE_BYTES + row * 272 + nq * 16),
                 B + (size_t)(k0 + row) * N + bn + nq * 8);
        }
        asm volatile("cp.async.commit_group;" ::: "memory");
    };

    issue(0);
    issue(1);

    // ldmatrix per-lane address components
    int tr = lane & 7;
    int q1 = (lane >> 3) & 1;
    int q2 = lane >> 4;

    for (int it = 0; it < NIT; it++) {
        asm volatile("cp.async.wait_group 1;" ::: "memory");
        __syncthreads();
        if (it + 2 < NIT) issue(it + 2);
        else asm volatile("cp.async.commit_group;" ::: "memory");

        uint32_t abase = sb + (uint32_t)(it % 3) * STAGE_BYTES;
        uint32_t bbase = abase + A_STAGE_BYTES;

        #pragma unroll
        for (int kt = 0; kt < 2; kt++) {
            unsigned af[2][4], bf[8][2];
            // A frags: rows wm*32 + fm*16 + tr + q1*8, col halves kt*16 + q2*8
            #pragma unroll
            for (int fm = 0; fm < 2; fm++) {
                int row = wm * 32 + fm * 16 + tr + q1 * 8;
                int colh = kt * 16 + q2 * 8;
                ldsm_x4(af[fm][0], af[fm][1], af[fm][2], af[fm][3],
                        abase + (uint32_t)(row * 80 + colh * 2));
            }
            // B frags (trans): k = kt*16 + tr + q1*8, n = wn*64 + fn2*16 + q2*8
            #pragma unroll
            for (int fn2 = 0; fn2 < 4; fn2++) {
                int kk = kt * 16 + tr + q1 * 8;
                int nn = wn * 64 + fn2 * 16 + q2 * 8;
                ldsm_x4_t(bf[fn2 * 2][0], bf[fn2 * 2][1], bf[fn2 * 2 + 1][0], bf[fn2 * 2 + 1][1],
                          bbase + (uint32_t)(kk * 272 + nn * 2));
            }
            #pragma unroll
            for (int fm = 0; fm < 2; fm++)
                #pragma unroll
                for (int fn = 0; fn < 8; fn++)
                    mma_f16(acc[fm][fn], af[fm], bf[fn][0], bf[fn][1]);
        }
    }

    // epilogue
    #pragma unroll
    for (int fm = 0; fm < 2; fm++) {
        int r_lo = bm + wm * 32 + fm * 16 + r;
        #pragma unroll
        for (int fn = 0; fn < 8; fn++) {
            int col = bn + wn * 64 + fn * 8 + 2 * c;
            float v0 = acc[fm][fn][0], v1 = acc[fm][fn][1];
            float v2 = acc[fm][fn][2], v3 = acc[fm][fn][3];
            if (BIAS) {
                float b0v = bias[col], b1v = bias[col + 1];
                v0 += b0v; v1 += b1v; v2 += b0v; v3 += b1v;
            }
            if (GELU_) { v0 = gelu_f(v0); v1 = gelu_f(v1); v2 = gelu_f(v2); v3 = gelu_f(v3); }
            if (RES) {
                float2 r0 = *(const float2*)(res + (size_t)r_lo * N + col);
                float2 r1 = *(const float2*)(res + (size_t)(r_lo + 8) * N + col);
                v0 += r0.x; v1 += r0.y; v2 += r1.x; v3 += r1.y;
            }
            if (HOUT) {
                __half* Ch = (__half*)C;
                *(uint32_t*)(Ch + (size_t)r_lo * N + col)       = pack_h2(v0, v1);
                *(uint32_t*)(Ch + (size_t)(r_lo + 8) * N + col) = pack_h2(v2, v3);
            } else {
                float* Cf = (float*)C;
                *(float2*)(Cf + (size_t)r_lo * N + col)       = make_float2(v0, v1);
                *(float2*)(Cf + (size_t)(r_lo + 8) * N + col) = make_float2(v2, v3);
            }
        }
    }
}

// ---------------- banded attention (tf32 mma, half I/O) ----------------
#define QP_PAD 68
#define V_PAD  72
#define ATTN_SMEM_WORDS (2 * 64 * QP_PAD + 64 * V_PAD + 258)

__global__ __launch_bounds__(128) void attn_mma(const __half* __restrict__ Q,
                                                const __half* __restrict__ Kb,
                                                const __half* __restrict__ Vb,
                                                const float* __restrict__ rel_emb,
                                                __half* __restrict__ O) {
    extern __shared__ unsigned smem_u[];
    unsigned (*Qs)[QP_PAD] = (unsigned(*)[QP_PAD])smem_u;            // also Ps
    unsigned (*Ks)[QP_PAD] = (unsigned(*)[QP_PAD])(smem_u + 64 * QP_PAD);
    unsigned (*Vs)[V_PAD]  = (unsigned(*)[V_PAD]) (smem_u + 2 * 64 * QP_PAD);
    float* bias_s = (float*)(smem_u + 2 * 64 * QP_PAD + 64 * V_PAD);

    int n = blockIdx.x, h = blockIdx.y;
    int tid = threadIdx.x, lane = tid & 31, wid = tid >> 5;
    int r = lane >> 2, c = lane & 3;

    for (int t = tid; t < 512; t += 128) {
        int i = t >> 3, d8 = (t & 7) * 8;
        uint4 v = *(const uint4*)(Q + (size_t)(n * 64 + i) * DM_ + h * 64 + d8);
        const __half2* hp = (const __half2*)&v;
        #pragma unroll
        for (int q = 0; q < 4; q++) {
            float2 f = __half22float2(hp[q]);
            Qs[i][d8 + 2 * q]     = f2tf32(f.x * 0.125f);
            Qs[i][d8 + 2 * q + 1] = f2tf32(f.y * 0.125f);
        }
    }
    for (int t = tid; t < 258; t += 128) bias_s[t] = rel_emb[t * H_ + h];
    __syncthreads();

    unsigned qf[8][4];
    int row0 = wid * 16 + r;
    #pragma unroll
    for (int kk = 0; kk < 8; kk++) {
        qf[kk][0] = Qs[row0][kk * 8 + c];
        qf[kk][1] = Qs[row0 + 8][kk * 8 + c];
        qf[kk][2] = Qs[row0][kk * 8 + c + 4];
        qf[kk][3] = Qs[row0 + 8][kk * 8 + c + 4];
    }

    float of[8][4];
    #pragma unroll
    for (int f = 0; f < 8; f++)
        #pragma unroll
        for (int e = 0; e < 4; e++) of[f][e] = 0.f;
    float m0 = -1e30f, m1 = -1e30f, l0 = 0.f, l1 = 0.f;

    int w0 = (n >= W_ - 1) ? 0 : (W_ - 1 - n);
    for (int w = w0; w < W_; w++) {
        int sb = n - (W_ - 1) + w;
        __syncthreads();
        for (int t = tid; t < 512; t += 128) {
            int j = t >> 3, d8 = (t & 7) * 8;
            uint4 kv = *(const uint4*)(Kb + (size_t)(sb * 64 + j) * DM_ + h * 64 + d8);
            uint4 vv = *(const uint4*)(Vb + (size_t)(sb * 64 + j) * DM_ + h * 64 + d8);
            const __half2* kp = (const __half2*)&kv;
            const __half2* vp = (const __half2*)&vv;
            #pragma unroll
            for (int q = 0; q < 4; q++) {
                float2 fk = __half22float2(kp[q]);
                float2 fv = __half22float2(vp[q]);
                Ks[j][d8 + 2 * q]     = f2tf32(fk.x);
                Ks[j][d8 + 2 * q + 1] = f2tf32(fk.y);
                Vs[j][d8 + 2 * q]     = f2tf32(fv.x);
                Vs[j][d8 + 2 * q + 1] = f2tf32(fv.y);
            }
        }
        __syncthreads();

        float sf[8][4];
        #pragma unroll
        for (int f = 0; f < 8; f++)
            #pragma unroll
            for (int e = 0; e < 4; e++) sf[f][e] = 0.f;
        #pragma unroll
        for (int kk = 0; kk < 8; kk++) {
            #pragma unroll
            for (int f = 0; f < 8; f++) {
                unsigned b0 = Ks[f * 8 + r][kk * 8 + c];
                unsigned b1 = Ks[f * 8 + r][kk * 8 + c + 4];
                mma_tf32(sf[f], qf[kk], b0, b1);
            }
        }

        int base = (W_ - 1 - w) * 64;
        bool last = (w == W_ - 1);
        float mx0 = -1e30f, mx1 = -1e30f;
        #pragma unroll
        for (int f = 0; f < 8; f++) {
            #pragma unroll
            for (int e = 0; e < 2; e++) {
                int j = f * 8 + 2 * c + e;
                int d0 = base + row0 - j;
                int d1 = d0 + 8;
                float v0 = sf[f][e]     + bias_s[max(min(d0, 256) + 1, 0)];
                float v1 = sf[f][e + 2] + bias_s[max(min(d1, 256) + 1, 0)];
                if (last && d0 < 0) v0 = -1e30f;
                if (last && d1 < 0) v1 = -1e30f;
                sf[f][e] = v0; sf[f][e + 2] = v1;
                mx0 = fmaxf(mx0, v0); mx1 = fmaxf(mx1, v1);
            }
        }
        mx0 = fmaxf(mx0, __shfl_xor_sync(0xffffffffu, mx0, 1));
        mx0 = fmaxf(mx0, __shfl_xor_sync(0xffffffffu, mx0, 2));
        mx1 = fmaxf(mx1, __shfl_xor_sync(0xffffffffu, mx1, 1));
        mx1 = fmaxf(mx1, __shfl_xor_sync(0xffffffffu, mx1, 2));
        float mn0 = fmaxf(m0, mx0), mn1 = fmaxf(m1, mx1);
        float sc0 = __expf(m0 - mn0), sc1 = __expf(m1 - mn1);
        m0 = mn0; m1 = mn1;

        float s0 = 0.f, s1 = 0.f;
        #pragma unroll
        for (int f = 0; f < 8; f++) {
            #pragma unroll
            for (int e = 0; e < 2; e++) {
                int col = f * 8 + 2 * c + e;
                float p0 = __expf(sf[f][e]     - mn0);
                float p1 = __expf(sf[f][e + 2] - mn1);
                s0 += p0; s1 += p1;
                Qs[row0][col]     = f2tf32(p0);
                Qs[row0 + 8][col] = f2tf32(p1);
            }
        }
        s0 += __shfl_xor_sync(0xffffffffu, s0, 1);
        s0 += __shfl_xor_sync(0xffffffffu, s0, 2);
        s1 += __shfl_xor_sync(0xffffffffu, s1, 1);
        s1 += __shfl_xor_sync(0xffffffffu, s1, 2);
        l0 = l0 * sc0 + s0;
        l1 = l1 * sc1 + s1;
        #pragma unroll
        for (int f = 0; f < 8; f++) {
            of[f][0] *= sc0; of[f][1] *= sc0;
            of[f][2] *= sc1; of[f][3] *= sc1;
        }
        __syncwarp();

        #pragma unroll
        for (int kk = 0; kk < 8; kk++) {
            unsigned pa[4];
            pa[0] = Qs[row0][kk * 8 + c];
            pa[1] = Qs[row0 + 8][kk * 8 + c];
            pa[2] = Qs[row0][kk * 8 + c + 4];
            pa[3] = Qs[row0 + 8][kk * 8 + c + 4];
            #pragma unroll
            for (int f = 0; f < 8; f++) {
                unsigned b0 = Vs[kk * 8 + c][f * 8 + r];
                unsigned b1 = Vs[kk * 8 + c + 4][f * 8 + r];
                mma_tf32(of[f], pa, b0, b1);
            }
        }
    }

    float invl0 = 1.f / l0, invl1 = 1.f / l1;
    #pragma unroll
    for (int f = 0; f < 8; f++) {
        int col = f * 8 + 2 * c;
        *(uint32_t*)(O + (size_t)(n * 64 + row0) * DM_ + h * 64 + col) =
            pack_h2(of[f][0] * invl0, of[f][1] * invl0);
        *(uint32_t*)(O + (size_t)(n * 64 + row0 + 8) * DM_ + h * 64 + col) =
            pack_h2(of[f][2] * invl1, of[f][3] * invl1);
    }
}

// ---------------- launch ----------------
extern "C" void kernel_launch(void* const* d_in, const int* in_sizes, int n_in,
                              void* d_out, int out_size) {
    (void)in_sizes; (void)n_in; (void)out_size;
    const float* x      = (const float*)d_in[0];
    const float* Wq     = (const float*)d_in[1];
    const float* Wk     = (const float*)d_in[2];
    const float* Wv     = (const float*)d_in[3];
    const float* Wo     = (const float*)d_in[4];
    const float* rel    = (const float*)d_in[5];
    const float* ln1g   = (const float*)d_in[6];
    const float* ln1b   = (const float*)d_in[7];
    const float* ln2g   = (const float*)d_in[8];
    const float* ln2b   = (const float*)d_in[9];
    const float* W1     = (const float*)d_in[10];
    const float* b1     = (const float*)d_in[11];
    const float* W2     = (const float*)d_in[12];
    const float* b2     = (const float*)d_in[13];
    float* out = (float*)d_out;

    __half *Hb, *Qb, *Kb, *Vb, *Ob, *Gb;
    float *X1;
    __half *WqH, *WkH, *WvH, *WoH, *W1H, *W2H;
    cudaGetSymbolAddress((void**)&Hb, g_H);
    cudaGetSymbolAddress((void**)&Qb, g_Q);
    cudaGetSymbolAddress((void**)&Kb, g_K);
    cudaGetSymbolAddress((void**)&Vb, g_V);
    cudaGetSymbolAddress((void**)&Ob, g_O);
    cudaGetSymbolAddress((void**)&X1, g_X1);
    cudaGetSymbolAddress((void**)&Gb, g_G);
    cudaGetSymbolAddress((void**)&WqH, g_WqH);
    cudaGetSymbolAddress((void**)&WkH, g_WkH);
    cudaGetSymbolAddress((void**)&WvH, g_WvH);
    cudaGetSymbolAddress((void**)&WoH, g_WoH);
    cudaGetSymbolAddress((void**)&W1H, g_W1H);
    cudaGetSymbolAddress((void**)&W2H, g_W2H);

    const int attn_smem = ATTN_SMEM_WORDS * 4;
    cudaFuncSetAttribute(attn_mma, cudaFuncAttributeMaxDynamicSharedMemorySize, attn_smem);
    cudaFuncSetAttribute(hgemm_pipe<false, false, false, true>,  cudaFuncAttributeMaxDynamicSharedMemorySize, PIPE_SMEM);
    cudaFuncSetAttribute(hgemm_pipe<false, true, false, false>,  cudaFuncAttributeMaxDynamicSharedMemorySize, PIPE_SMEM);
    cudaFuncSetAttribute(hgemm_pipe<true, false, true, true>,    cudaFuncAttributeMaxDynamicSharedMemorySize, PIPE_SMEM);
    cudaFuncSetAttribute(hgemm_pipe<true, true, false, false>,   cudaFuncAttributeMaxDynamicSharedMemorySize, PIPE_SMEM);

    // 0. convert all weights to half (one launch)
    cvt_all<<<(12 * SMALL8 + 255) / 256 / 1 , 256>>>(Wq, Wk, Wv, Wo, W1, W2,
                                                     WqH, WkH, WvH, WoH, W1H, W2H);

    // 1. h = LN1(x)  (half)
    ln_kernel<<<L_, 256>>>(x, ln1g, ln1b, Hb);

    // 2. fused Q,K,V GEMMs
    hgemm_pipe<false, false, false, true><<<dim3(DM_ / 128, L_ / 128, 3), 256, PIPE_SMEM>>>(
        Hb, WqH, WkH, WvH, Qb, Kb, Vb, nullptr, nullptr, L_, DM_, DM_);

    // 3. banded attention (half I/O)
    attn_mma<<<dim3(NB_, H_), 128, attn_smem>>>(Qb, Kb, Vb, rel, Ob);

    // 4. x1 = x + O @ Wo  (fp32 out)
    hgemm_pipe<false, true, false, false><<<dim3(DM_ / 128, L_ / 128, 1), 256, PIPE_SMEM>>>(
        Ob, WoH, WoH, WoH, X1, X1, X1, nullptr, x, L_, DM_, DM_);

    // 5. h2 = LN2(x1)  (half)
    ln_kernel<<<L_, 256>>>(X1, ln2g, ln2b, Hb);

    // 6. G = gelu(h2 @ W1 + b1)  (half)
    hgemm_pipe<true, false, true, true><<<dim3(DFF_ / 128, L_ / 128, 1), 256, PIPE_SMEM>>>(
        Hb, W1H, W1H, W1H, Gb, Gb, Gb, b1, nullptr, L_, DFF_, DM_);

    // 7. out = x1 + G @ W2 + b2  (fp32 out)
    hgemm_pipe<true, true, false, false><<<dim3(DM_ / 128, L_ / 128, 1), 256, PIPE_SMEM>>>(
        Gb, W2H, W2H, W2H, out, out, out, b2, X1, L_, DM_, DFF_);
}

// round 9
// speedup vs baseline: 7.8498x; 1.1708x over previous
#include <cuda_runtime.h>
#include <cuda_fp16.h>
#include <stdint.h>
#include <math.h>

#define L_   4096
#define DM_  1024
#define H_   16
#define DH_  64
#define BS_  64
#define W_   16
#define NB_  64
#define DFF_ 4096

// ---------------- scratch (static __device__ arrays; no allocations) ----------------
__device__ __half g_H [L_ * DM_];   // LN output (half)
__device__ __half g_Q [L_ * DM_];
__device__ __half g_K [L_ * DM_];
__device__ __half g_V [L_ * DM_];
__device__ __half g_O [L_ * DM_];   // attention output (half)
__device__ float  g_X1[L_ * DM_];   // x + attn@Wo (fp32)
__device__ __half g_G [L_ * DFF_];  // gelu(h2@W1+b1) (half)
// half weights, same [K][N] layout
__device__ __half g_WqH[DM_ * DM_];
__device__ __half g_WkH[DM_ * DM_];
__device__ __half g_WvH[DM_ * DM_];
__device__ __half g_WoH[DM_ * DM_];
__device__ __half g_W1H[DM_ * DFF_];
__device__ __half g_W2H[DFF_ * DM_];

// ---------------- small helpers ----------------
__device__ __forceinline__ float block_sum(float val, float* red) {
    int t = threadIdx.x;
    #pragma unroll
    for (int o = 16; o > 0; o >>= 1) val += __shfl_xor_sync(0xffffffffu, val, o);
    __syncthreads();
    if ((t & 31) == 0) red[t >> 5] = val;
    __syncthreads();
    if (t == 0) {
        float z = 0.f;
        #pragma unroll
        for (int i = 0; i < 8; i++) z += red[i];
        red[0] = z;
    }
    __syncthreads();
    return red[0];
}

__device__ __forceinline__ float gelu_f(float x) {
    float x3 = x * x * x;
    return 0.5f * x * (1.f + tanhf(0.7978845608028654f * (x + 0.044715f * x3)));
}

__device__ __forceinline__ void mma_f16(float* d, const unsigned* a, unsigned b0, unsigned b1) {
    asm volatile(
        "mma.sync.aligned.m16n8k16.row.col.f32.f16.f16.f32 "
        "{%0,%1,%2,%3}, {%4,%5,%6,%7}, {%8,%9}, {%0,%1,%2,%3};\n"
        : "+f"(d[0]), "+f"(d[1]), "+f"(d[2]), "+f"(d[3])
        : "r"(a[0]), "r"(a[1]), "r"(a[2]), "r"(a[3]), "r"(b0), "r"(b1));
}

__device__ __forceinline__ void ldsm_x4(unsigned& r0, unsigned& r1, unsigned& r2, unsigned& r3,
                                        uint32_t addr) {
    asm volatile("ldmatrix.sync.aligned.m8n8.x4.shared.b16 {%0,%1,%2,%3}, [%4];"
                 : "=r"(r0), "=r"(r1), "=r"(r2), "=r"(r3) : "r"(addr));
}
__device__ __forceinline__ void ldsm_x4_t(unsigned& r0, unsigned& r1, unsigned& r2, unsigned& r3,
                                          uint32_t addr) {
    asm volatile("ldmatrix.sync.aligned.m8n8.x4.trans.shared.b16 {%0,%1,%2,%3}, [%4];"
                 : "=r"(r0), "=r"(r1), "=r"(r2), "=r"(r3) : "r"(addr));
}

__device__ __forceinline__ uint32_t s2u(const void* p) {
    return (uint32_t)__cvta_generic_to_shared(p);
}

__device__ __forceinline__ void cp16(uint32_t dst, const void* src) {
    asm volatile("cp.async.cg.shared.global [%0], [%1], 16;" :: "r"(dst), "l"(src));
}

__device__ __forceinline__ uint32_t pack_h2(float lo, float hi) {
    __half2 h = __floats2half2_rn(lo, hi);
    return *reinterpret_cast<uint32_t*>(&h);
}

// ---------------- LayerNorm (fp32 in, half out) ----------------
__global__ __launch_bounds__(256) void ln_kernel(const float* __restrict__ x,
                                                 const float* __restrict__ g,
                                                 const float* __restrict__ b,
                                                 __half* __restrict__ out) {
    __shared__ float red[8];
    int row = blockIdx.x;
    const float* xr = x + (size_t)row * DM_;
    int t = threadIdx.x;
    float v[4];
    float s = 0.f;
    #pragma unroll
    for (int i = 0; i < 4; i++) { v[i] = xr[t + i * 256]; s += v[i]; }
    float mean = block_sum(s, red) * (1.f / DM_);
    float s2 = 0.f;
    #pragma unroll
    for (int i = 0; i < 4; i++) { float d = v[i] - mean; s2 += d * d; }
    float var = block_sum(s2, red) * (1.f / DM_);
    float inv = rsqrtf(var + 1e-5f);
    __half* orow = out + (size_t)row * DM_;
    #pragma unroll
    for (int i = 0; i < 4; i++) {
        int c = t + i * 256;
        orow[c] = __float2half((v[i] - mean) * inv * g[c] + b[c]);
    }
}

// ---------------- fused weight convert fp32 -> half (all 6 weights, 1 launch) --------
#define SMALL8 (DM_ * DM_ / 8)
__global__ __launch_bounds__(256) void cvt_all(
        const float* __restrict__ s0, const float* __restrict__ s1,
        const float* __restrict__ s2, const float* __restrict__ s3,
        const float* __restrict__ s4, const float* __restrict__ s5,
        __half* __restrict__ d0, __half* __restrict__ d1,
        __half* __restrict__ d2, __half* __restrict__ d3,
        __half* __restrict__ d4, __half* __restrict__ d5) {
    long i = (long)blockIdx.x * 256 + threadIdx.x;   // unit = 8 floats
    const float* src; __half* dst; long off;
    if      (i < 1 * SMALL8)               { src = s0; dst = d0; off = i; }
    else if (i < 2 * SMALL8)               { src = s1; dst = d1; off = i - 1 * SMALL8; }
    else if (i < 3 * SMALL8)               { src = s2; dst = d2; off = i - 2 * SMALL8; }
    else if (i < 4 * SMALL8)               { src = s3; dst = d3; off = i - 3 * SMALL8; }
    else if (i < 4 * SMALL8 + 4 * SMALL8)  { src = s4; dst = d4; off = i - 4 * SMALL8; }
    else                                   { src = s5; dst = d5; off = i - 8 * SMALL8; }
    long e = off * 8;
    float4 a = *(const float4*)(src + e);
    float4 b = *(const float4*)(src + e + 4);
    uint4 o;
    o.x = pack_h2(a.x, a.y); o.y = pack_h2(a.z, a.w);
    o.z = pack_h2(b.x, b.y); o.w = pack_h2(b.z, b.w);
    *(uint4*)(dst + e) = o;
}

// ---------------- ldmatrix fp16 GEMM: C = act(A @ B + bias) + res ----------------
#define A_STAGE_BYTES (128 * 80)
#define B_STAGE_BYTES (32 * 272)
#define STAGE_BYTES (A_STAGE_BYTES + B_STAGE_BYTES)
#define PIPE_SMEM (3 * STAGE_BYTES)

template<bool BIAS, bool RES, bool GELU_, bool HOUT>
__global__ __launch_bounds__(256, 2) void hgemm_pipe(
        const __half* __restrict__ A,
        const __half* __restrict__ B0, const __half* __restrict__ B1, const __half* __restrict__ B2,
        void* __restrict__ C0, void* __restrict__ C1, void* __restrict__ C2,
        const float* __restrict__ bias,
        const float* __restrict__ res,
        int M, int N, int K) {
    extern __shared__ char smem_c[];
    uint32_t sb = s2u(smem_c);

    int tid  = threadIdx.x;
    int lane = tid & 31;
    int wid  = tid >> 5;
    int bm = blockIdx.y * 128, bn = blockIdx.x * 128;
    int wm = wid >> 1, wn = wid & 1;
    int r = lane >> 2, c = lane & 3;

    const __half* B = (blockIdx.z == 0) ? B0 : (blockIdx.z == 1) ? B1 : B2;
    void*         C = (blockIdx.z == 0) ? C0 : (blockIdx.z == 1) ? C1 : C2;

    float acc[2][8][4];
    #pragma unroll
    for (int fm = 0; fm < 2; fm++)
        #pragma unroll
        for (int fn = 0; fn < 8; fn++)
            #pragma unroll
            for (int i = 0; i < 4; i++) acc[fm][fn][i] = 0.f;

    int NIT = K >> 5;

    auto issue = [&](int it) {
        uint32_t base = sb + (uint32_t)(it % 3) * STAGE_BYTES;
        int k0 = it << 5;
        #pragma unroll
        for (int p = 0; p < 2; p++) {
            int idx = p * 256 + tid;
            int row = idx >> 2, aq = idx & 3;
            cp16(base + (uint32_t)(row * 80 + aq * 16),
                 A + (size_t)(bm + row) * K + k0 + aq * 8);
        }
        #pragma unroll
        for (int p = 0; p < 2; p++) {
            int idx = p * 256 + tid;
            int row = idx >> 4, nq = idx & 15;
            cp16(base + (uint32_t)(A_STAGE_BYTES + row * 272 + nq * 16),
                 B + (size_t)(k0 + row) * N + bn + nq * 8);
        }
        asm volatile("cp.async.commit_group;" ::: "memory");
    };

    issue(0);
    issue(1);

    int tr = lane & 7;
    int q1 = (lane >> 3) & 1;
    int q2 = lane >> 4;

    for (int it = 0; it < NIT; it++) {
        asm volatile("cp.async.wait_group 1;" ::: "memory");
        __syncthreads();
        if (it + 2 < NIT) issue(it + 2);
        else asm volatile("cp.async.commit_group;" ::: "memory");

        uint32_t abase = sb + (uint32_t)(it % 3) * STAGE_BYTES;
        uint32_t bbase = abase + A_STAGE_BYTES;

        #pragma unroll
        for (int kt = 0; kt < 2; kt++) {
            unsigned af[2][4], bf[8][2];
            #pragma unroll
            for (int fm = 0; fm < 2; fm++) {
                int row = wm * 32 + fm * 16 + tr + q1 * 8;
                int colh = kt * 16 + q2 * 8;
                ldsm_x4(af[fm][0], af[fm][1], af[fm][2], af[fm][3],
                        abase + (uint32_t)(row * 80 + colh * 2));
            }
            #pragma unroll
            for (int fn2 = 0; fn2 < 4; fn2++) {
                int kk = kt * 16 + tr + q1 * 8;
                int nn = wn * 64 + fn2 * 16 + q2 * 8;
                ldsm_x4_t(bf[fn2 * 2][0], bf[fn2 * 2][1], bf[fn2 * 2 + 1][0], bf[fn2 * 2 + 1][1],
                          bbase + (uint32_t)(kk * 272 + nn * 2));
            }
            #pragma unroll
            for (int fm = 0; fm < 2; fm++)
                #pragma unroll
                for (int fn = 0; fn < 8; fn++)
                    mma_f16(acc[fm][fn], af[fm], bf[fn][0], bf[fn][1]);
        }
    }

    // epilogue
    #pragma unroll
    for (int fm = 0; fm < 2; fm++) {
        int r_lo = bm + wm * 32 + fm * 16 + r;
        #pragma unroll
        for (int fn = 0; fn < 8; fn++) {
            int col = bn + wn * 64 + fn * 8 + 2 * c;
            float v0 = acc[fm][fn][0], v1 = acc[fm][fn][1];
            float v2 = acc[fm][fn][2], v3 = acc[fm][fn][3];
            if (BIAS) {
                float b0v = bias[col], b1v = bias[col + 1];
                v0 += b0v; v1 += b1v; v2 += b0v; v3 += b1v;
            }
            if (GELU_) { v0 = gelu_f(v0); v1 = gelu_f(v1); v2 = gelu_f(v2); v3 = gelu_f(v3); }
            if (RES) {
                float2 r0 = *(const float2*)(res + (size_t)r_lo * N + col);
                float2 r1 = *(const float2*)(res + (size_t)(r_lo + 8) * N + col);
                v0 += r0.x; v1 += r0.y; v2 += r1.x; v3 += r1.y;
            }
            if (HOUT) {
                __half* Ch = (__half*)C;
                *(uint32_t*)(Ch + (size_t)r_lo * N + col)       = pack_h2(v0, v1);
                *(uint32_t*)(Ch + (size_t)(r_lo + 8) * N + col) = pack_h2(v2, v3);
            } else {
                float* Cf = (float*)C;
                *(float2*)(Cf + (size_t)r_lo * N + col)       = make_float2(v0, v1);
                *(float2*)(Cf + (size_t)(r_lo + 8) * N + col) = make_float2(v2, v3);
            }
        }
    }
}

// ---------------- banded attention: fp16 mma + cp.async double-buffered K/V ----------
// grid (NB, H), 128 threads = 4 warps; warp w owns query rows [w*16, w*16+16).
// smem halves, row stride 72 (144B): QP[64][72] (Q then P), K[2][64][72], V[2][64][72],
// bias[258] floats.
#define SP_BYTES 144
#define TILE_BYTES (64 * SP_BYTES)          /* 9216 */
#define QP_OFF 0
#define K_OFF  TILE_BYTES
#define V_OFF  (TILE_BYTES * 3)
#define BIAS_OFF (TILE_BYTES * 5)
#define ATTN_SMEM (BIAS_OFF + 258 * 4)

__global__ __launch_bounds__(128) void attn_h(const __half* __restrict__ Q,
                                              const __half* __restrict__ Kb,
                                              const __half* __restrict__ Vb,
                                              const float* __restrict__ rel_emb,
                                              __half* __restrict__ O) {
    extern __shared__ char sm[];
    uint32_t sb = s2u(sm);
    float* bias_s = (float*)(sm + BIAS_OFF);

    int n = blockIdx.x, h = blockIdx.y;
    int tid = threadIdx.x, lane = tid & 31, wid = tid >> 5;
    int r = lane >> 2, c = lane & 3;
    int tr = lane & 7, q1 = (lane >> 3) & 1, q2 = lane >> 4;

    // Q tile -> smem (raw half copy)
    #pragma unroll
    for (int p = 0; p < 4; p++) {
        int idx = p * 128 + tid;
        int row = idx >> 3, nq = idx & 7;
        cp16(sb + QP_OFF + (uint32_t)(row * SP_BYTES + nq * 16),
             Q + (size_t)(n * 64 + row) * DM_ + h * 64 + nq * 8);
    }
    for (int t = tid; t < 258; t += 128) bias_s[t] = rel_emb[t * H_ + h];

    int w0 = (n >= W_ - 1) ? 0 : (W_ - 1 - n);

    auto issueKV = [&](int w, int b) {
        int sbk = n - (W_ - 1) + w;
        const __half* kp = Kb + (size_t)(sbk * 64) * DM_ + h * 64;
        const __half* vp = Vb + (size_t)(sbk * 64) * DM_ + h * 64;
        uint32_t kb = sb + K_OFF + (uint32_t)b * TILE_BYTES;
        uint32_t vb = sb + V_OFF + (uint32_t)b * TILE_BYTES;
        #pragma unroll
        for (int p = 0; p < 4; p++) {
            int idx = p * 128 + tid;
            int row = idx >> 3, nq = idx & 7;
            cp16(kb + (uint32_t)(row * SP_BYTES + nq * 16), kp + (size_t)row * DM_ + nq * 8);
            cp16(vb + (uint32_t)(row * SP_BYTES + nq * 16), vp + (size_t)row * DM_ + nq * 8);
        }
        asm volatile("cp.async.commit_group;" ::: "memory");
    };

    issueKV(w0, 0);
    asm volatile("cp.async.wait_group 0;" ::: "memory");
    __syncthreads();

    // Q fragments into registers (persist across windows); QP becomes P afterwards
    unsigned qf[4][4];
    {
        int arow = wid * 16 + tr + q1 * 8;
        #pragma unroll
        for (int kt = 0; kt < 4; kt++) {
            int colh = kt * 16 + q2 * 8;
            ldsm_x4(qf[kt][0], qf[kt][1], qf[kt][2], qf[kt][3],
                    sb + QP_OFF + (uint32_t)(arow * SP_BYTES + colh * 2));
        }
    }

    float of[8][4];
    #pragma unroll
    for (int f = 0; f < 8; f++)
        #pragma unroll
        for (int e = 0; e < 4; e++) of[f][e] = 0.f;
    float m0 = -1e30f, m1 = -1e30f, l0 = 0.f, l1 = 0.f;

    int row0 = wid * 16 + r;
    int buf = 0;

    for (int w = w0; w < W_; w++) {
        if (w + 1 < W_) issueKV(w + 1, buf ^ 1);
        uint32_t kbase = sb + K_OFF + (uint32_t)buf * TILE_BYTES;
        uint32_t vbase = sb + V_OFF + (uint32_t)buf * TILE_BYTES;

        // S = Q @ K^T : B fragments direct from K[j][d] via non-trans ldmatrix
        float sf[8][4];
        #pragma unroll
        for (int f = 0; f < 8; f++)
            #pragma unroll
            for (int e = 0; e < 4; e++) sf[f][e] = 0.f;
        #pragma unroll
        for (int kt = 0; kt < 4; kt++) {
            unsigned bf[8][2];
            #pragma unroll
            for (int jb = 0; jb < 4; jb++) {
                uint32_t addr = kbase + (uint32_t)((jb * 16 + q2 * 8 + tr) * SP_BYTES
                                                   + (kt * 16 + q1 * 8) * 2);
                ldsm_x4(bf[jb * 2][0], bf[jb * 2][1], bf[jb * 2 + 1][0], bf[jb * 2 + 1][1], addr);
            }
            #pragma unroll
            for (int fn = 0; fn < 8; fn++)
                mma_f16(sf[fn], qf[kt], bf[fn][0], bf[fn][1]);
        }

        // scale + bias + mask + register flash softmax
        int base = (W_ - 1 - w) * 64;
        bool last = (w == W_ - 1);
        float mx0 = -1e30f, mx1 = -1e30f;
        #pragma unroll
        for (int f = 0; f < 8; f++) {
            #pragma unroll
            for (int e = 0; e < 2; e++) {
                int j = f * 8 + 2 * c + e;
                int d0 = base + row0 - j;
                int d1 = d0 + 8;
                float v0 = fmaf(sf[f][e],     0.125f, bias_s[max(min(d0, 256) + 1, 0)]);
                float v1 = fmaf(sf[f][e + 2], 0.125f, bias_s[max(min(d1, 256) + 1, 0)]);
                if (last && d0 < 0) v0 = -1e30f;
                if (last && d1 < 0) v1 = -1e30f;
                sf[f][e] = v0; sf[f][e + 2] = v1;
                mx0 = fmaxf(mx0, v0); mx1 = fmaxf(mx1, v1);
            }
        }
        mx0 = fmaxf(mx0, __shfl_xor_sync(0xffffffffu, mx0, 1));
        mx0 = fmaxf(mx0, __shfl_xor_sync(0xffffffffu, mx0, 2));
        mx1 = fmaxf(mx1, __shfl_xor_sync(0xffffffffu, mx1, 1));
        mx1 = fmaxf(mx1, __shfl_xor_sync(0xffffffffu, mx1, 2));
        float mn0 = fmaxf(m0, mx0), mn1 = fmaxf(m1, mx1);
        float sc0 = __expf(m0 - mn0), sc1 = __expf(m1 - mn1);
        m0 = mn0; m1 = mn1;

        float s0 = 0.f, s1 = 0.f;
        #pragma unroll
        for (int f = 0; f < 8; f++) {
            float p00 = __expf(sf[f][0] - mn0);
            float p01 = __expf(sf[f][1] - mn0);
            float p10 = __expf(sf[f][2] - mn1);
            float p11 = __expf(sf[f][3] - mn1);
            s0 += p00 + p01; s1 += p10 + p11;
            int colh = f * 8 + 2 * c;
            *(uint32_t*)(sm + QP_OFF + row0 * SP_BYTES + colh * 2)       = pack_h2(p00, p01);
            *(uint32_t*)(sm + QP_OFF + (row0 + 8) * SP_BYTES + colh * 2) = pack_h2(p10, p11);
        }
        s0 += __shfl_xor_sync(0xffffffffu, s0, 1);
        s0 += __shfl_xor_sync(0xffffffffu, s0, 2);
        s1 += __shfl_xor_sync(0xffffffffu, s1, 1);
        s1 += __shfl_xor_sync(0xffffffffu, s1, 2);
        l0 = l0 * sc0 + s0;
        l1 = l1 * sc1 + s1;
        #pragma unroll
        for (int f = 0; f < 8; f++) {
            of[f][0] *= sc0; of[f][1] *= sc0;
            of[f][2] *= sc1; of[f][3] *= sc1;
        }
        __syncwarp();

        // O += P @ V : A = P (warp-private rows), B = V via trans ldmatrix
        #pragma unroll
        for (int kt = 0; kt < 4; kt++) {
            unsigned pf[4];
            ldsm_x4(pf[0], pf[1], pf[2], pf[3],
                    sb + QP_OFF + (uint32_t)((wid * 16 + tr + q1 * 8) * SP_BYTES
                                             + (kt * 16 + q2 * 8) * 2));
            unsigned bf[8][2];
            #pragma unroll
            for (int fn2 = 0; fn2 < 4; fn2++) {
                uint32_t addr = vbase + (uint32_t)((kt * 16 + tr + q1 * 8) * SP_BYTES
                                                   + (fn2 * 16 + q2 * 8) * 2);
                ldsm_x4_t(bf[fn2 * 2][0], bf[fn2 * 2][1], bf[fn2 * 2 + 1][0], bf[fn2 * 2 + 1][1], addr);
            }
            #pragma unroll
            for (int fn = 0; fn < 8; fn++)
                mma_f16(of[fn], pf, bf[fn][0], bf[fn][1]);
        }

        if (w + 1 < W_) {
            asm volatile("cp.async.wait_group 0;" ::: "memory");
            __syncthreads();
        }
        buf ^= 1;
    }

    float invl0 = 1.f / l0, invl1 = 1.f / l1;
    #pragma unroll
    for (int f = 0; f < 8; f++) {
        int col = f * 8 + 2 * c;
        *(uint32_t*)(O + (size_t)(n * 64 + row0) * DM_ + h * 64 + col) =
            pack_h2(of[f][0] * invl0, of[f][1] * invl0);
        *(uint32_t*)(O + (size_t)(n * 64 + row0 + 8) * DM_ + h * 64 + col) =
            pack_h2(of[f][2] * invl1, of[f][3] * invl1);
    }
}

// ---------------- launch ----------------
extern "C" void kernel_launch(void* const* d_in, const int* in_sizes, int n_in,
                              void* d_out, int out_size) {
    (void)in_sizes; (void)n_in; (void)out_size;
    const float* x      = (const float*)d_in[0];
    const float* Wq     = (const float*)d_in[1];
    const float* Wk     = (const float*)d_in[2];
    const float* Wv     = (const float*)d_in[3];
    const float* Wo     = (const float*)d_in[4];
    const float* rel    = (const float*)d_in[5];
    const float* ln1g   = (const float*)d_in[6];
    const float* ln1b   = (const float*)d_in[7];
    const float* ln2g   = (const float*)d_in[8];
    const float* ln2b   = (const float*)d_in[9];
    const float* W1     = (const float*)d_in[10];
    const float* b1     = (const float*)d_in[11];
    const float* W2     = (const float*)d_in[12];
    const float* b2     = (const float*)d_in[13];
    float* out = (float*)d_out;

    __half *Hb, *Qb, *Kb, *Vb, *Ob, *Gb;
    float *X1;
    __half *WqH, *WkH, *WvH, *WoH, *W1H, *W2H;
    cudaGetSymbolAddress((void**)&Hb, g_H);
    cudaGetSymbolAddress((void**)&Qb, g_Q);
    cudaGetSymbolAddress((void**)&Kb, g_K);
    cudaGetSymbolAddress((void**)&Vb, g_V);
    cudaGetSymbolAddress((void**)&Ob, g_O);
    cudaGetSymbolAddress((void**)&X1, g_X1);
    cudaGetSymbolAddress((void**)&Gb, g_G);
    cudaGetSymbolAddress((void**)&WqH, g_WqH);
    cudaGetSymbolAddress((void**)&WkH, g_WkH);
    cudaGetSymbolAddress((void**)&WvH, g_WvH);
    cudaGetSymbolAddress((void**)&WoH, g_WoH);
    cudaGetSymbolAddress((void**)&W1H, g_W1H);
    cudaGetSymbolAddress((void**)&W2H, g_W2H);

    cudaFuncSetAttribute(attn_h, cudaFuncAttributeMaxDynamicSharedMemorySize, ATTN_SMEM);
    cudaFuncSetAttribute(hgemm_pipe<false, false, false, true>,  cudaFuncAttributeMaxDynamicSharedMemorySize, PIPE_SMEM);
    cudaFuncSetAttribute(hgemm_pipe<false, true, false, false>,  cudaFuncAttributeMaxDynamicSharedMemorySize, PIPE_SMEM);
    cudaFuncSetAttribute(hgemm_pipe<true, false, true, true>,    cudaFuncAttributeMaxDynamicSharedMemorySize, PIPE_SMEM);
    cudaFuncSetAttribute(hgemm_pipe<true, true, false, false>,   cudaFuncAttributeMaxDynamicSharedMemorySize, PIPE_SMEM);

    // 0. convert all weights to half (one launch)
    cvt_all<<<(12 * SMALL8 + 255) / 256, 256>>>(Wq, Wk, Wv, Wo, W1, W2,
                                                WqH, WkH, WvH, WoH, W1H, W2H);

    // 1. h = LN1(x)  (half)
    ln_kernel<<<L_, 256>>>(x, ln1g, ln1b, Hb);

    // 2. fused Q,K,V GEMMs
    hgemm_pipe<false, false, false, true><<<dim3(DM_ / 128, L_ / 128, 3), 256, PIPE_SMEM>>>(
        Hb, WqH, WkH, WvH, Qb, Kb, Vb, nullptr, nullptr, L_, DM_, DM_);

    // 3. banded attention (fp16 mma, cp.async pipelined)
    attn_h<<<dim3(NB_, H_), 128, ATTN_SMEM>>>(Qb, Kb, Vb, rel, Ob);

    // 4. x1 = x + O @ Wo  (fp32 out)
    hgemm_pipe<false, true, false, false><<<dim3(DM_ / 128, L_ / 128, 1), 256, PIPE_SMEM>>>(
        Ob, WoH, WoH, WoH, X1, X1, X1, nullptr, x, L_, DM_, DM_);

    // 5. h2 = LN2(x1)  (half)
    ln_kernel<<<L_, 256>>>(X1, ln2g, ln2b, Hb);

    // 6. G = gelu(h2 @ W1 + b1)  (half)
    hgemm_pipe<true, false, true, true><<<dim3(DFF_ / 128, L_ / 128, 1), 256, PIPE_SMEM>>>(
        Hb, W1H, W1H, W1H, Gb, Gb, Gb, b1, nullptr, L_, DFF_, DM_);

    // 7. out = x1 + G @ W2 + b2  (fp32 out)
    hgemm_pipe<true, true, false, false><<<dim3(DM_ / 128, L_ / 128, 1), 256, PIPE_SMEM>>>(
        Gb, W2H, W2H, W2H, out, out, out, b2, X1, L_, DM_, DFF_);
}

// round 10
// speedup vs baseline: 8.3040x; 1.0579x over previous
#include <cuda_runtime.h>
#include <cuda_fp16.h>
#include <stdint.h>
#include <math.h>

#define L_   4096
#define DM_  1024
#define H_   16
#define DH_  64
#define BS_  64
#define W_   16
#define NB_  64
#define DFF_ 4096

// ---------------- scratch (static __device__ arrays; no allocations) ----------------
__device__ __half g_H [L_ * DM_];
__device__ __half g_Q [L_ * DM_];
__device__ __half g_K [L_ * DM_];
__device__ __half g_V [L_ * DM_];
__device__ __half g_O [L_ * DM_];
__device__ float  g_X1[L_ * DM_];
__device__ __half g_G [L_ * DFF_];
__device__ __half g_WqH[DM_ * DM_];
__device__ __half g_WkH[DM_ * DM_];
__device__ __half g_WvH[DM_ * DM_];
__device__ __half g_WoH[DM_ * DM_];
__device__ __half g_W1H[DM_ * DFF_];
__device__ __half g_W2H[DFF_ * DM_];

// ---------------- small helpers ----------------
__device__ __forceinline__ float block_sum(float val, float* red) {
    int t = threadIdx.x;
    #pragma unroll
    for (int o = 16; o > 0; o >>= 1) val += __shfl_xor_sync(0xffffffffu, val, o);
    __syncthreads();
    if ((t & 31) == 0) red[t >> 5] = val;
    __syncthreads();
    if (t == 0) {
        float z = 0.f;
        #pragma unroll
        for (int i = 0; i < 8; i++) z += red[i];
        red[0] = z;
    }
    __syncthreads();
    return red[0];
}

__device__ __forceinline__ float gelu_f(float x) {
    float x3 = x * x * x;
    return 0.5f * x * (1.f + tanhf(0.7978845608028654f * (x + 0.044715f * x3)));
}

__device__ __forceinline__ void mma_f16(float* d, const unsigned* a, unsigned b0, unsigned b1) {
    asm volatile(
        "mma.sync.aligned.m16n8k16.row.col.f32.f16.f16.f32 "
        "{%0,%1,%2,%3}, {%4,%5,%6,%7}, {%8,%9}, {%0,%1,%2,%3};\n"
        : "+f"(d[0]), "+f"(d[1]), "+f"(d[2]), "+f"(d[3])
        : "r"(a[0]), "r"(a[1]), "r"(a[2]), "r"(a[3]), "r"(b0), "r"(b1));
}

__device__ __forceinline__ void ldsm_x4(unsigned& r0, unsigned& r1, unsigned& r2, unsigned& r3,
                                        uint32_t addr) {
    asm volatile("ldmatrix.sync.aligned.m8n8.x4.shared.b16 {%0,%1,%2,%3}, [%4];"
                 : "=r"(r0), "=r"(r1), "=r"(r2), "=r"(r3) : "r"(addr));
}
__device__ __forceinline__ void ldsm_x4_t(unsigned& r0, unsigned& r1, unsigned& r2, unsigned& r3,
                                          uint32_t addr) {
    asm volatile("ldmatrix.sync.aligned.m8n8.x4.trans.shared.b16 {%0,%1,%2,%3}, [%4];"
                 : "=r"(r0), "=r"(r1), "=r"(r2), "=r"(r3) : "r"(addr));
}

__device__ __forceinline__ uint32_t s2u(const void* p) {
    return (uint32_t)__cvta_generic_to_shared(p);
}

__device__ __forceinline__ void cp16(uint32_t dst, const void* src) {
    asm volatile("cp.async.cg.shared.global [%0], [%1], 16;" :: "r"(dst), "l"(src));
}

__device__ __forceinline__ uint32_t pack_h2(float lo, float hi) {
    __half2 h = __floats2half2_rn(lo, hi);
    return *reinterpret_cast<uint32_t*>(&h);
}

// ---------------- LayerNorm (fp32 in, half out) ----------------
__global__ __launch_bounds__(256) void ln_kernel(const float* __restrict__ x,
                                                 const float* __restrict__ g,
                                                 const float* __restrict__ b,
                                                 __half* __restrict__ out) {
    __shared__ float red[8];
    int row = blockIdx.x;
    const float* xr = x + (size_t)row * DM_;
    int t = threadIdx.x;
    float v[4];
    float s = 0.f;
    #pragma unroll
    for (int i = 0; i < 4; i++) { v[i] = xr[t + i * 256]; s += v[i]; }
    float mean = block_sum(s, red) * (1.f / DM_);
    float s2 = 0.f;
    #pragma unroll
    for (int i = 0; i < 4; i++) { float d = v[i] - mean; s2 += d * d; }
    float var = block_sum(s2, red) * (1.f / DM_);
    float inv = rsqrtf(var + 1e-5f);
    __half* orow = out + (size_t)row * DM_;
    #pragma unroll
    for (int i = 0; i < 4; i++) {
        int c = t + i * 256;
        orow[c] = __float2half((v[i] - mean) * inv * g[c] + b[c]);
    }
}

// ---------------- fused weight convert fp32 -> half ----------------
#define SMALL8 (DM_ * DM_ / 8)
__global__ __launch_bounds__(256) void cvt_all(
        const float* __restrict__ s0, const float* __restrict__ s1,
        const float* __restrict__ s2, const float* __restrict__ s3,
        const float* __restrict__ s4, const float* __restrict__ s5,
        __half* __restrict__ d0, __half* __restrict__ d1,
        __half* __restrict__ d2, __half* __restrict__ d3,
        __half* __restrict__ d4, __half* __restrict__ d5) {
    long i = (long)blockIdx.x * 256 + threadIdx.x;
    const float* src; __half* dst; long off;
    if      (i < 1 * SMALL8)               { src = s0; dst = d0; off = i; }
    else if (i < 2 * SMALL8)               { src = s1; dst = d1; off = i - 1 * SMALL8; }
    else if (i < 3 * SMALL8)               { src = s2; dst = d2; off = i - 2 * SMALL8; }
    else if (i < 4 * SMALL8)               { src = s3; dst = d3; off = i - 3 * SMALL8; }
    else if (i < 4 * SMALL8 + 4 * SMALL8)  { src = s4; dst = d4; off = i - 4 * SMALL8; }
    else                                   { src = s5; dst = d5; off = i - 8 * SMALL8; }
    long e = off * 8;
    float4 a = *(const float4*)(src + e);
    float4 b = *(const float4*)(src + e + 4);
    uint4 o;
    o.x = pack_h2(a.x, a.y); o.y = pack_h2(a.z, a.w);
    o.z = pack_h2(b.x, b.y); o.w = pack_h2(b.z, b.w);
    *(uint4*)(dst + e) = o;
}

// ---------------- ldmatrix fp16 GEMM, BK=64: C = act(A @ B + bias) + res -------------
// A[M][K] half row-major (smem row 144B), B[K][N] half row-major (smem row 272B).
#define A_STAGE_BYTES (128 * 144)
#define B_STAGE_BYTES (64 * 272)
#define STAGE_BYTES (A_STAGE_BYTES + B_STAGE_BYTES)
#define PIPE_SMEM (3 * STAGE_BYTES)

template<bool BIAS, bool RES, bool GELU_, bool HOUT>
__global__ __launch_bounds__(256, 2) void hgemm_pipe(
        const __half* __restrict__ A,
        const __half* __restrict__ B0, const __half* __restrict__ B1, const __half* __restrict__ B2,
        void* __restrict__ C0, void* __restrict__ C1, void* __restrict__ C2,
        const float* __restrict__ bias,
        const float* __restrict__ res,
        int M, int N, int K) {
    extern __shared__ char smem_c[];
    uint32_t sb = s2u(smem_c);

    int tid  = threadIdx.x;
    int lane = tid & 31;
    int wid  = tid >> 5;
    int bm = blockIdx.y * 128, bn = blockIdx.x * 128;
    int wm = wid >> 1, wn = wid & 1;
    int r = lane >> 2, c = lane & 3;

    const __half* B = (blockIdx.z == 0) ? B0 : (blockIdx.z == 1) ? B1 : B2;
    void*         C = (blockIdx.z == 0) ? C0 : (blockIdx.z == 1) ? C1 : C2;

    float acc[2][8][4];
    #pragma unroll
    for (int fm = 0; fm < 2; fm++)
        #pragma unroll
        for (int fn = 0; fn < 8; fn++)
            #pragma unroll
            for (int i = 0; i < 4; i++) acc[fm][fn][i] = 0.f;

    int NIT = K >> 6;

    auto issue = [&](int it) {
        uint32_t base = sb + (uint32_t)(it % 3) * STAGE_BYTES;
        int k0 = it << 6;
        #pragma unroll
        for (int p = 0; p < 4; p++) {
            int idx = p * 256 + tid;
            int row = idx >> 3, aq = idx & 7;
            cp16(base + (uint32_t)(row * 144 + aq * 16),
                 A + (size_t)(bm + row) * K + k0 + aq * 8);
        }
        #pragma unroll
        for (int p = 0; p < 4; p++) {
            int idx = p * 256 + tid;
            int row = idx >> 4, nq = idx & 15;
            cp16(base + (uint32_t)(A_STAGE_BYTES + row * 272 + nq * 16),
                 B + (size_t)(k0 + row) * N + bn + nq * 8);
        }
        asm volatile("cp.async.commit_group;" ::: "memory");
    };

    issue(0);
    issue(1);

    int tr = lane & 7;
    int q1 = (lane >> 3) & 1;
    int q2 = lane >> 4;

    for (int it = 0; it < NIT; it++) {
        asm volatile("cp.async.wait_group 1;" ::: "memory");
        __syncthreads();
        if (it + 2 < NIT) issue(it + 2);
        else asm volatile("cp.async.commit_group;" ::: "memory");

        uint32_t abase = sb + (uint32_t)(it % 3) * STAGE_BYTES;
        uint32_t bbase = abase + A_STAGE_BYTES;

        #pragma unroll
        for (int kt = 0; kt < 4; kt++) {
            unsigned af[2][4], bf[8][2];
            #pragma unroll
            for (int fm = 0; fm < 2; fm++) {
                int row = wm * 32 + fm * 16 + tr + q1 * 8;
                int colh = kt * 16 + q2 * 8;
                ldsm_x4(af[fm][0], af[fm][1], af[fm][2], af[fm][3],
                        abase + (uint32_t)(row * 144 + colh * 2));
            }
            #pragma unroll
            for (int fn2 = 0; fn2 < 4; fn2++) {
                int kk = kt * 16 + tr + q1 * 8;
                int nn = wn * 64 + fn2 * 16 + q2 * 8;
                ldsm_x4_t(bf[fn2 * 2][0], bf[fn2 * 2][1], bf[fn2 * 2 + 1][0], bf[fn2 * 2 + 1][1],
                          bbase + (uint32_t)(kk * 272 + nn * 2));
            }
            #pragma unroll
            for (int fm = 0; fm < 2; fm++)
                #pragma unroll
                for (int fn = 0; fn < 8; fn++)
                    mma_f16(acc[fm][fn], af[fm], bf[fn][0], bf[fn][1]);
        }
    }

    // epilogue
    #pragma unroll
    for (int fm = 0; fm < 2; fm++) {
        int r_lo = bm + wm * 32 + fm * 16 + r;
        #pragma unroll
        for (int fn = 0; fn < 8; fn++) {
            int col = bn + wn * 64 + fn * 8 + 2 * c;
            float v0 = acc[fm][fn][0], v1 = acc[fm][fn][1];
            float v2 = acc[fm][fn][2], v3 = acc[fm][fn][3];
            if (BIAS) {
                float b0v = bias[col], b1v = bias[col + 1];
                v0 += b0v; v1 += b1v; v2 += b0v; v3 += b1v;
            }
            if (GELU_) { v0 = gelu_f(v0); v1 = gelu_f(v1); v2 = gelu_f(v2); v3 = gelu_f(v3); }
            if (RES) {
                float2 r0 = *(const float2*)(res + (size_t)r_lo * N + col);
                float2 r1 = *(const float2*)(res + (size_t)(r_lo + 8) * N + col);
                v0 += r0.x; v1 += r0.y; v2 += r1.x; v3 += r1.y;
            }
            if (HOUT) {
                __half* Ch = (__half*)C;
                *(uint32_t*)(Ch + (size_t)r_lo * N + col)       = pack_h2(v0, v1);
                *(uint32_t*)(Ch + (size_t)(r_lo + 8) * N + col) = pack_h2(v2, v3);
            } else {
                float* Cf = (float*)C;
                *(float2*)(Cf + (size_t)r_lo * N + col)       = make_float2(v0, v1);
                *(float2*)(Cf + (size_t)(r_lo + 8) * N + col) = make_float2(v2, v3);
            }
        }
    }
}

// ---------------- banded attention: fp16 mma, register-resident P ----------------
#define SP_BYTES 144
#define TILE_BYTES (64 * SP_BYTES)
#define QP_OFF 0
#define K_OFF  TILE_BYTES
#define V_OFF  (TILE_BYTES * 3)
#define BIAS_OFF (TILE_BYTES * 5)
#define ATTN_SMEM (BIAS_OFF + 258 * 4)

__global__ __launch_bounds__(128) void attn_h(const __half* __restrict__ Q,
                                              const __half* __restrict__ Kb,
                                              const __half* __restrict__ Vb,
                                              const float* __restrict__ rel_emb,
                                              __half* __restrict__ O) {
    extern __shared__ char sm[];
    uint32_t sb = s2u(sm);
    float* bias_s = (float*)(sm + BIAS_OFF);

    int n = blockIdx.x, h = blockIdx.y;
    int tid = threadIdx.x, lane = tid & 31, wid = tid >> 5;
    int r = lane >> 2, c = lane & 3;
    int tr = lane & 7, q1 = (lane >> 3) & 1, q2 = lane >> 4;

    #pragma unroll
    for (int p = 0; p < 4; p++) {
        int idx = p * 128 + tid;
        int row = idx >> 3, nq = idx & 7;
        cp16(sb + QP_OFF + (uint32_t)(row * SP_BYTES + nq * 16),
             Q + (size_t)(n * 64 + row) * DM_ + h * 64 + nq * 8);
    }
    for (int t = tid; t < 258; t += 128) bias_s[t] = rel_emb[t * H_ + h];

    int w0 = (n >= W_ - 1) ? 0 : (W_ - 1 - n);

    auto issueKV = [&](int w, int b) {
        int sbk = n - (W_ - 1) + w;
        const __half* kp = Kb + (size_t)(sbk * 64) * DM_ + h * 64;
        const __half* vp = Vb + (size_t)(sbk * 64) * DM_ + h * 64;
        uint32_t kb = sb + K_OFF + (uint32_t)b * TILE_BYTES;
        uint32_t vb = sb + V_OFF + (uint32_t)b * TILE_BYTES;
        #pragma unroll
        for (int p = 0; p < 4; p++) {
            int idx = p * 128 + tid;
            int row = idx >> 3, nq = idx & 7;
            cp16(kb + (uint32_t)(row * SP_BYTES + nq * 16), kp + (size_t)row * DM_ + nq * 8);
            cp16(vb + (uint32_t)(row * SP_BYTES + nq * 16), vp + (size_t)row * DM_ + nq * 8);
        }
        asm volatile("cp.async.commit_group;" ::: "memory");
    };

    issueKV(w0, 0);
    asm volatile("cp.async.wait_group 0;" ::: "memory");
    __syncthreads();

    // Q fragments (persist across windows)
    unsigned qf[4][4];
    {
        int arow = wid * 16 + tr + q1 * 8;
        #pragma unroll
        for (int kt = 0; kt < 4; kt++) {
            int colh = kt * 16 + q2 * 8;
            ldsm_x4(qf[kt][0], qf[kt][1], qf[kt][2], qf[kt][3],
                    sb + QP_OFF + (uint32_t)(arow * SP_BYTES + colh * 2));
        }
    }

    float of[8][4];
    #pragma unroll
    for (int f = 0; f < 8; f++)
        #pragma unroll
        for (int e = 0; e < 4; e++) of[f][e] = 0.f;
    float m0 = -1e30f, m1 = -1e30f, l0 = 0.f, l1 = 0.f;

    int row0 = wid * 16 + r;
    int buf = 0;
    float cb = 0.f;  // filled after bias_s visible (post first __syncthreads above)
    cb = bias_s[257];

    for (int w = w0; w < W_; w++) {
        if (w + 1 < W_) issueKV(w + 1, buf ^ 1);
        uint32_t kbase = sb + K_OFF + (uint32_t)buf * TILE_BYTES;
        uint32_t vbase = sb + V_OFF + (uint32_t)buf * TILE_BYTES;

        // S = Q @ K^T
        float sf[8][4];
        #pragma unroll
        for (int f = 0; f < 8; f++)
            #pragma unroll
            for (int e = 0; e < 4; e++) sf[f][e] = 0.f;
        #pragma unroll
        for (int kt = 0; kt < 4; kt++) {
            unsigned bf[8][2];
            #pragma unroll
            for (int jb = 0; jb < 4; jb++) {
                uint32_t addr = kbase + (uint32_t)((jb * 16 + q2 * 8 + tr) * SP_BYTES
                                                   + (kt * 16 + q1 * 8) * 2);
                ldsm_x4(bf[jb * 2][0], bf[jb * 2][1], bf[jb * 2 + 1][0], bf[jb * 2 + 1][1], addr);
            }
            #pragma unroll
            for (int fn = 0; fn < 8; fn++)
                mma_f16(sf[fn], qf[kt], bf[fn][0], bf[fn][1]);
        }

        // scale + bias + mask
        int base = (W_ - 1 - w) * 64;
        bool far  = (w <= W_ - 6);      // all deltas >= 257 -> constant clip bias
        bool last = (w == W_ - 1);
        float mx0 = -1e30f, mx1 = -1e30f;
        if (far) {
            #pragma unroll
            for (int f = 0; f < 8; f++) {
                #pragma unroll
                for (int e = 0; e < 2; e++) {
                    float v0 = fmaf(sf[f][e],     0.125f, cb);
                    float v1 = fmaf(sf[f][e + 2], 0.125f, cb);
                    sf[f][e] = v0; sf[f][e + 2] = v1;
                    mx0 = fmaxf(mx0, v0); mx1 = fmaxf(mx1, v1);
                }
            }
        } else {
            #pragma unroll
            for (int f = 0; f < 8; f++) {
                #pragma unroll
                for (int e = 0; e < 2; e++) {
                    int j = f * 8 + 2 * c + e;
                    int d0 = base + row0 - j;
                    int d1 = d0 + 8;
                    float v0 = fmaf(sf[f][e],     0.125f, bias_s[max(min(d0, 256) + 1, 0)]);
                    float v1 = fmaf(sf[f][e + 2], 0.125f, bias_s[max(min(d1, 256) + 1, 0)]);
                    if (last && d0 < 0) v0 = -1e30f;
                    if (last && d1 < 0) v1 = -1e30f;
                    sf[f][e] = v0; sf[f][e + 2] = v1;
                    mx0 = fmaxf(mx0, v0); mx1 = fmaxf(mx1, v1);
                }
            }
        }
        mx0 = fmaxf(mx0, __shfl_xor_sync(0xffffffffu, mx0, 1));
        mx0 = fmaxf(mx0, __shfl_xor_sync(0xffffffffu, mx0, 2));
        mx1 = fmaxf(mx1, __shfl_xor_sync(0xffffffffu, mx1, 1));
        mx1 = fmaxf(mx1, __shfl_xor_sync(0xffffffffu, mx1, 2));
        float mn0 = fmaxf(m0, mx0), mn1 = fmaxf(m1, mx1);
        float sc0 = __expf(m0 - mn0), sc1 = __expf(m1 - mn1);
        m0 = mn0; m1 = mn1;

        // exp + pack P directly into PV A-fragments (S frag layout == A frag layout)
        unsigned pa[4][4];
        float s0 = 0.f, s1 = 0.f;
        #pragma unroll
        for (int f = 0; f < 8; f++) {
            float p00 = __expf(sf[f][0] - mn0);
            float p01 = __expf(sf[f][1] - mn0);
            float p10 = __expf(sf[f][2] - mn1);
            float p11 = __expf(sf[f][3] - mn1);
            s0 += p00 + p01; s1 += p10 + p11;
            pa[f >> 1][(f & 1) * 2 + 0] = pack_h2(p00, p01);
            pa[f >> 1][(f & 1) * 2 + 1] = pack_h2(p10, p11);
        }
        s0 += __shfl_xor_sync(0xffffffffu, s0, 1);
        s0 += __shfl_xor_sync(0xffffffffu, s0, 2);
        s1 += __shfl_xor_sync(0xffffffffu, s1, 1);
        s1 += __shfl_xor_sync(0xffffffffu, s1, 2);
        l0 = l0 * sc0 + s0;
        l1 = l1 * sc1 + s1;
        #pragma unroll
        for (int f = 0; f < 8; f++) {
            of[f][0] *= sc0; of[f][1] *= sc0;
            of[f][2] *= sc1; of[f][3] *= sc1;
        }

        // O += P @ V  (A from registers, B = V via trans ldmatrix)
        #pragma unroll
        for (int kt = 0; kt < 4; kt++) {
            unsigned bf[8][2];
            #pragma unroll
            for (int fn2 = 0; fn2 < 4; fn2++) {
                uint32_t addr = vbase + (uint32_t)((kt * 16 + tr + q1 * 8) * SP_BYTES
                                                   + (fn2 * 16 + q2 * 8) * 2);
                ldsm_x4_t(bf[fn2 * 2][0], bf[fn2 * 2][1], bf[fn2 * 2 + 1][0], bf[fn2 * 2 + 1][1], addr);
            }
            #pragma unroll
            for (int fn = 0; fn < 8; fn++)
                mma_f16(of[fn], pa[kt], bf[fn][0], bf[fn][1]);
        }

        if (w + 1 < W_) {
            asm volatile("cp.async.wait_group 0;" ::: "memory");
            __syncthreads();
        }
        buf ^= 1;
    }

    float invl0 = 1.f / l0, invl1 = 1.f / l1;
    #pragma unroll
    for (int f = 0; f < 8; f++) {
        int col = f * 8 + 2 * c;
        *(uint32_t*)(O + (size_t)(n * 64 + row0) * DM_ + h * 64 + col) =
            pack_h2(of[f][0] * invl0, of[f][1] * invl0);
        *(uint32_t*)(O + (size_t)(n * 64 + row0 + 8) * DM_ + h * 64 + col) =
            pack_h2(of[f][2] * invl1, of[f][3] * invl1);
    }
}

// ---------------- launch ----------------
extern "C" void kernel_launch(void* const* d_in, const int* in_sizes, int n_in,
                              void* d_out, int out_size) {
    (void)in_sizes; (void)n_in; (void)out_size;
    const float* x      = (const float*)d_in[0];
    const float* Wq     = (const float*)d_in[1];
    const float* Wk     = (const float*)d_in[2];
    const float* Wv     = (const float*)d_in[3];
    const float* Wo     = (const float*)d_in[4];
    const float* rel    = (const float*)d_in[5];
    const float* ln1g   = (const float*)d_in[6];
    const float* ln1b   = (const float*)d_in[7];
    const float* ln2g   = (const float*)d_in[8];
    const float* ln2b   = (const float*)d_in[9];
    const float* W1     = (const float*)d_in[10];
    const float* b1     = (const float*)d_in[11];
    const float* W2     = (const float*)d_in[12];
    const float* b2     = (const float*)d_in[13];
    float* out = (float*)d_out;

    __half *Hb, *Qb, *Kb, *Vb, *Ob, *Gb;
    float *X1;
    __half *WqH, *WkH, *WvH, *WoH, *W1H, *W2H;
    cudaGetSymbolAddress((void**)&Hb, g_H);
    cudaGetSymbolAddress((void**)&Qb, g_Q);
    cudaGetSymbolAddress((void**)&Kb, g_K);
    cudaGetSymbolAddress((void**)&Vb, g_V);
    cudaGetSymbolAddress((void**)&Ob, g_O);
    cudaGetSymbolAddress((void**)&X1, g_X1);
    cudaGetSymbolAddress((void**)&Gb, g_G);
    cudaGetSymbolAddress((void**)&WqH, g_WqH);
    cudaGetSymbolAddress((void**)&WkH, g_WkH);
    cudaGetSymbolAddress((void**)&WvH, g_WvH);
    cudaGetSymbolAddress((void**)&WoH, g_WoH);
    cudaGetSymbolAddress((void**)&W1H, g_W1H);
    cudaGetSymbolAddress((void**)&W2H, g_W2H);

    cudaFuncSetAttribute(attn_h, cudaFuncAttributeMaxDynamicSharedMemorySize, ATTN_SMEM);
    cudaFuncSetAttribute(hgemm_pipe<false, false, false, true>,  cudaFuncAttributeMaxDynamicSharedMemorySize, PIPE_SMEM);
    cudaFuncSetAttribute(hgemm_pipe<false, true, false, false>,  cudaFuncAttributeMaxDynamicSharedMemorySize, PIPE_SMEM);
    cudaFuncSetAttribute(hgemm_pipe<true, false, true, true>,    cudaFuncAttributeMaxDynamicSharedMemorySize, PIPE_SMEM);
    cudaFuncSetAttribute(hgemm_pipe<true, true, false, false>,   cudaFuncAttributeMaxDynamicSharedMemorySize, PIPE_SMEM);

    // 0. convert all weights to half (one launch)
    cvt_all<<<(12 * SMALL8 + 255) / 256, 256>>>(Wq, Wk, Wv, Wo, W1, W2,
                                                WqH, WkH, WvH, WoH, W1H, W2H);

    // 1. h = LN1(x)
    ln_kernel<<<L_, 256>>>(x, ln1g, ln1b, Hb);

    // 2. fused Q,K,V GEMMs
    hgemm_pipe<false, false, false, true><<<dim3(DM_ / 128, L_ / 128, 3), 256, PIPE_SMEM>>>(
        Hb, WqH, WkH, WvH, Qb, Kb, Vb, nullptr, nullptr, L_, DM_, DM_);

    // 3. banded attention
    attn_h<<<dim3(NB_, H_), 128, ATTN_SMEM>>>(Qb, Kb, Vb, rel, Ob);

    // 4. x1 = x + O @ Wo
    hgemm_pipe<false, true, false, false><<<dim3(DM_ / 128, L_ / 128, 1), 256, PIPE_SMEM>>>(
        Ob, WoH, WoH, WoH, X1, X1, X1, nullptr, x, L_, DM_, DM_);

    // 5. h2 = LN2(x1)
    ln_kernel<<<L_, 256>>>(X1, ln2g, ln2b, Hb);

    // 6. G = gelu(h2 @ W1 + b1)
    hgemm_pipe<true, false, true, true><<<dim3(DFF_ / 128, L_ / 128, 1), 256, PIPE_SMEM>>>(
        Hb, W1H, W1H, W1H, Gb, Gb, Gb, b1, nullptr, L_, DFF_, DM_);

    // 7. out = x1 + G @ W2 + b2
    hgemm_pipe<true, true, false, false><<<dim3(DM_ / 128, L_ / 128, 1), 256, PIPE_SMEM>>>(
        Gb, W2H, W2H, W2H, out, out, out, b2, X1, L_, DM_, DFF_);
}